// round 10
// baseline (speedup 1.0000x reference)
#include <cuda_runtime.h>
#include <cuda_bf16.h>
#include <cstdint>

// Problem constants
#define L_LAYERS 2
#define U_DIM    256
#define U4       (U_DIM / 4)
#define NL_LAB   64
#define B_DIM    128
#define T_DIM    128
#define DEG      5
#define BT       (B_DIM * T_DIM)          // 16384 nodes
#define E_EDGES  (BT * DEG)               // 81920
#define WSZ      (U_DIM * U_DIM)          // 65536 floats per weight matrix

// ---------------------------------------------------------------------------
// Scratch (device globals — no allocation allowed)
// ---------------------------------------------------------------------------
__device__ float g_X0[BT * U_DIM];
__device__ float g_X1[BT * U_DIM];
__device__ float g_Xtf[BT * U_DIM];               // tf32-rounded copy of X
__device__ float g_Wtf[L_LAYERS * 3 * WSZ];       // tf32-rounded weights [l][sel][K][N]
__device__ float g_XVin[BT * U_DIM];
__device__ float g_XVout[BT * U_DIM];
__device__ float g_XVloop[BT * U_DIM];
__device__ float g_gin[BT];
__device__ float g_gout[BT];
__device__ float g_gloop[BT];
__device__ float g_enc[B_DIM * U_DIM];

// ---------------------------------------------------------------------------
// helpers
// ---------------------------------------------------------------------------
__device__ __forceinline__ uint32_t f2tf32(float f) {
    uint32_t r;
    asm("cvt.rna.tf32.f32 %0, %1;" : "=r"(r) : "f"(f));
    return r;
}

__device__ __forceinline__ float4 cvt4(float4 v) {
    float4 o;
    o.x = __uint_as_float(f2tf32(v.x));
    o.y = __uint_as_float(f2tf32(v.y));
    o.z = __uint_as_float(f2tf32(v.z));
    o.w = __uint_as_float(f2tf32(v.w));
    return o;
}

__device__ __forceinline__ void mma_tf32(float* d, const uint32_t* a,
                                         const uint32_t* b) {
    asm volatile(
        "mma.sync.aligned.m16n8k8.row.col.f32.tf32.tf32.f32 "
        "{%0,%1,%2,%3}, {%4,%5,%6,%7}, {%8,%9}, {%0,%1,%2,%3};\n"
        : "+f"(d[0]), "+f"(d[1]), "+f"(d[2]), "+f"(d[3])
        : "r"(a[0]), "r"(a[1]), "r"(a[2]), "r"(a[3]), "r"(b[0]), "r"(b[1]));
}

__device__ __forceinline__ void cp16(void* dst, const void* src) {
    uint32_t d = (uint32_t)__cvta_generic_to_shared(dst);
    asm volatile("cp.async.cg.shared.global [%0], [%1], 16;\n"
                 :: "r"(d), "l"(src));
}
#define CP_COMMIT() asm volatile("cp.async.commit_group;\n" ::: "memory")
#define CP_WAIT1()  asm volatile("cp.async.wait_group 1;\n" ::: "memory")
#define CP_WAIT0()  asm volatile("cp.async.wait_group 0;\n" ::: "memory")

// ---------------------------------------------------------------------------
// 0) Weight conversion: all L*3 weight matrices -> tf32 bits, once.
// ---------------------------------------------------------------------------
__global__ void cvtw_k(const float* __restrict__ Vin,
                       const float* __restrict__ Vout,
                       const float* __restrict__ Wloop,
                       float* __restrict__ out)
{
    int idx = blockIdx.x * 256 + threadIdx.x;     // float4 index
    int l   = idx / (3 * WSZ / 4);
    int r   = idx % (3 * WSZ / 4);
    int sel = r / (WSZ / 4);
    int e4  = r % (WSZ / 4);
    const float* src = (sel == 0) ? Vin : ((sel == 1) ? Vout : Wloop);
    float4 v = reinterpret_cast<const float4*>(src + (size_t)l * WSZ)[e4];
    reinterpret_cast<float4*>(out)[idx] = cvt4(v);
}

// ---------------------------------------------------------------------------
// 1) Embedding gather: X[n=b*T+t] = emb[src[t,b]]; also tf32 copy.
// ---------------------------------------------------------------------------
__global__ void embed_k(const int* __restrict__ src,
                        const float* __restrict__ emb,
                        float* __restrict__ X,
                        float* __restrict__ Xtf)
{
    int grp = threadIdx.x >> 6;
    int n   = blockIdx.x * 4 + grp;
    int lu  = threadIdx.x & 63;
    int b = n / T_DIM, t = n % T_DIM;
    int tok = src[t * B_DIM + b];
    float4 v = reinterpret_cast<const float4*>(emb)[(size_t)tok * U4 + lu];
    reinterpret_cast<float4*>(X)[(size_t)n * U4 + lu]   = v;
    reinterpret_cast<float4*>(Xtf)[(size_t)n * U4 + lu] = cvt4(v);
}

// ---------------------------------------------------------------------------
// 2) Fused TF32 GEMM + gates. 1D grid of EXACTLY 888 blocks = 3 full waves
//    at 2 CTAs/SM x 148 SMs = 296 slots.
//      bid in [0,768): GEMM. x = bid&127 (m-tile), y = bid>>7 in [0,6):
//                      sel=y>>1 picks W/C, (y&1)*128 picks N half.
//                      128x128 tile, BK=16, 3-stage cp.async, 1 barrier/tile,
//                      16 warps (4Mx4N), warp tile 32x32.
//      bid in [768,888): gate GEMVs, grid-stride over nodes (120 blocks).
// ---------------------------------------------------------------------------
#define GBM 128
#define GBN 128
#define GBK 16
#define NT  (U_DIM / GBK)     // 16 k-tiles
#define GTHREADS 512
#define GEMM_BLOCKS 768
#define GATE_BLOCKS 120
#define TOTAL_BLOCKS (GEMM_BLOCKS + GATE_BLOCKS)   // 888 = 296*3
#define A_STAGE_F (GBM * (GBK + 4))     // 2560 floats
#define B_STAGE_F (GBK * (GBN + 8))     // 2176 floats
#define SMEM_DYN  (3 * (A_STAGE_F + B_STAGE_F) * 4)   // 56,832 B

__global__ __launch_bounds__(GTHREADS, 2)
void gemm_gate_k(const float* __restrict__ Atf,
                 const float* __restrict__ Wtf,   // [3][WSZ] for this layer
                 float* __restrict__ C0, float* __restrict__ C1,
                 float* __restrict__ C2,
                 const float* __restrict__ Aorig,
                 const float* __restrict__ vgin,
                 const float* __restrict__ vgout,
                 const float* __restrict__ wgl,
                 float* __restrict__ gin, float* __restrict__ gout,
                 float* __restrict__ gloop)
{
    const int bid = blockIdx.x;

    // ---------------- gate slice (grid-stride) ----------------
    if (bid >= GEMM_BLOCKS) {
        int gblk = bid - GEMM_BLOCKS;           // 0..119
        int warp = threadIdx.x >> 5;            // 0..15
        int lane = threadIdx.x & 31;
        const float4* v0 = reinterpret_cast<const float4*>(vgin);
        const float4* v1 = reinterpret_cast<const float4*>(vgout);
        const float4* v2 = reinterpret_cast<const float4*>(wgl);
        const int stride = GATE_BLOCKS * 16;    // 1920 warps total
#pragma unroll 1
        for (int n = gblk * 16 + warp; n < BT; n += stride) {
            const float4* xr =
                reinterpret_cast<const float4*>(Aorig + (size_t)n * U_DIM);
            float s0 = 0.f, s1 = 0.f, s2 = 0.f;
#pragma unroll
            for (int k = lane; k < U4; k += 32) {
                float4 x = xr[k];
                float4 a = v0[k], b = v1[k], c = v2[k];
                s0 += x.x * a.x + x.y * a.y + x.z * a.z + x.w * a.w;
                s1 += x.x * b.x + x.y * b.y + x.z * b.z + x.w * b.w;
                s2 += x.x * c.x + x.y * c.y + x.z * c.z + x.w * c.w;
            }
#pragma unroll
            for (int off = 16; off > 0; off >>= 1) {
                s0 += __shfl_down_sync(0xffffffffu, s0, off);
                s1 += __shfl_down_sync(0xffffffffu, s1, off);
                s2 += __shfl_down_sync(0xffffffffu, s2, off);
            }
            if (lane == 0) { gin[n] = s0; gout[n] = s1; gloop[n] = s2; }
        }
        return;
    }

    // ---------------- GEMM slice ----------------
    const int xb      = bid & 127;
    const int yb      = bid >> 7;              // 0..5
    const int sel     = yb >> 1;
    const int colbase = (yb & 1) * GBN;
    const float* __restrict__ W = Wtf + (size_t)sel * WSZ;
    float* __restrict__ C       = (sel == 0) ? C0 : ((sel == 1) ? C1 : C2);
    const int mbase = xb * GBM;

    // dynamic smem: 3-stage A and B tiles
    extern __shared__ __align__(16) float dsm[];
    float (*As)[GBM][GBK + 4] =
        reinterpret_cast<float (*)[GBM][GBK + 4]>(dsm);
    float (*Bs)[GBK][GBN + 8] =
        reinterpret_cast<float (*)[GBK][GBN + 8]>(dsm + 3 * A_STAGE_F);

    const int tid  = threadIdx.x;
    const int lane = tid & 31;
    const int warp = tid >> 5;
    const int wm   = (warp & 3) * 32;          // warp M offset
    const int wn   = (warp >> 2) * 32;         // warp N offset
    const int g    = lane >> 2;                // 0..7
    const int t    = lane & 3;                 // 0..3

    // cp.async: exactly one 16B per thread per operand per tile
    const int aRow = tid >> 2;                 // 0..127
    const int aK4  = (tid & 3) * 4;            // 0,4,8,12
    const int bK   = tid >> 5;                 // 0..15
    const int bN4  = (tid & 31) * 4;           // 0..124

    const float* Abase = Atf + (size_t)(mbase + aRow) * U_DIM + aK4;
    const float* Wbase = W + (size_t)bK * U_DIM + colbase + bN4;

    float acc[2][4][4];
#pragma unroll
    for (int mi = 0; mi < 2; mi++)
#pragma unroll
        for (int ni = 0; ni < 4; ni++)
#pragma unroll
            for (int c = 0; c < 4; c++) acc[mi][ni][c] = 0.f;

    // prologue: tiles 0 and 1 into stages 0 and 1
    cp16(&As[0][aRow][aK4], Abase);
    cp16(&Bs[0][bK][bN4],   Wbase);
    CP_COMMIT();
    cp16(&As[1][aRow][aK4], Abase + GBK);
    cp16(&Bs[1][bK][bN4],   Wbase + (size_t)GBK * U_DIM);
    CP_COMMIT();

#pragma unroll 1
    for (int tile = 0; tile < NT; tile++) {
        if (tile < NT - 1) { CP_WAIT1(); } else { CP_WAIT0(); }
        __syncthreads();   // single barrier: tile data visible, stage (tile+2)%3 free

        int nxt = tile + 2;
        if (nxt < NT) {
            int s  = nxt % 3;
            int k0 = nxt * GBK;
            cp16(&As[s][aRow][aK4], Abase + k0);
            cp16(&Bs[s][bK][bN4],   Wbase + (size_t)k0 * U_DIM);
            CP_COMMIT();
        }

        const int st = tile % 3;
#pragma unroll
        for (int ks = 0; ks < GBK; ks += 8) {
            uint32_t afr[2][4];
#pragma unroll
            for (int mi = 0; mi < 2; mi++) {
                int m0 = wm + mi * 16;
                afr[mi][0] = __float_as_uint(As[st][m0 + g][ks + t]);
                afr[mi][1] = __float_as_uint(As[st][m0 + g + 8][ks + t]);
                afr[mi][2] = __float_as_uint(As[st][m0 + g][ks + t + 4]);
                afr[mi][3] = __float_as_uint(As[st][m0 + g + 8][ks + t + 4]);
            }
            uint32_t bfr[4][2];
#pragma unroll
            for (int ni = 0; ni < 4; ni++) {
                int n0 = wn + ni * 8 + g;
                bfr[ni][0] = __float_as_uint(Bs[st][ks + t][n0]);
                bfr[ni][1] = __float_as_uint(Bs[st][ks + t + 4][n0]);
            }
#pragma unroll
            for (int mi = 0; mi < 2; mi++)
#pragma unroll
                for (int ni = 0; ni < 4; ni++)
                    mma_tf32(acc[mi][ni], afr[mi], bfr[ni]);
        }
    }

    // epilogue
#pragma unroll
    for (int mi = 0; mi < 2; mi++) {
#pragma unroll
        for (int ni = 0; ni < 4; ni++) {
            int row = mbase + wm + mi * 16 + g;
            int col = colbase + wn + ni * 8 + 2 * t;
            float2 v0 = make_float2(acc[mi][ni][0], acc[mi][ni][1]);
            float2 v1 = make_float2(acc[mi][ni][2], acc[mi][ni][3]);
            *reinterpret_cast<float2*>(&C[(size_t)row * U_DIM + col])       = v0;
            *reinterpret_cast<float2*>(&C[(size_t)(row + 8) * U_DIM + col]) = v1;
        }
    }
}

// ---------------------------------------------------------------------------
// 3) Edge aggregation, float4: 64 threads/node, 4 nodes/block.
// ---------------------------------------------------------------------------
__global__ __launch_bounds__(256)
void agg_k(const float* __restrict__ XVin,
           const float* __restrict__ XVout,
           const float* __restrict__ XVloop,
           const float* __restrict__ gin,
           const float* __restrict__ gout,
           const float* __restrict__ gloop,
           const int* __restrict__ arc_in,
           const int* __restrict__ arc_out,
           const int* __restrict__ lab_in,
           const int* __restrict__ lab_out,
           const float* __restrict__ b_in,
           const float* __restrict__ bg_in,
           const float* __restrict__ b_out,
           const float* __restrict__ bg_out,
           const float* __restrict__ mask_in,
           const float* __restrict__ mask_out,
           const float* __restrict__ mask_loop,
           const float* __restrict__ sent_mask,
           float* __restrict__ Y, float* __restrict__ Ytf, int tb_layout)
{
    int grp = threadIdx.x >> 6;
    int n   = blockIdx.x * 4 + grp;
    int lu  = threadIdx.x & 63;

    __shared__ float p_in[4][DEG], p_out[4][DEG], p_loop[4];
    __shared__ int   s_in[4][DEG], s_out[4][DEG], l_in[4][DEG], l_out[4][DEG];

    if (lu < DEG) {
        int d = lu, e = n * DEG + d;
        int si = arc_in[e] * T_DIM + arc_in[E_EDGES + e];
        int li = lab_in[e];
        float gi = gin[si] + bg_in[li];
        p_in[grp][d] = (1.f / (1.f + __expf(-gi))) * mask_in[n * DEG + d];
        s_in[grp][d] = si; l_in[grp][d] = li;
    } else if (lu < 2 * DEG) {
        int d = lu - DEG, e = n * DEG + d;
        int so = arc_out[e] * T_DIM + arc_out[E_EDGES + e];
        int lo = lab_out[e];
        float go = gout[so] + bg_out[lo];
        p_out[grp][d] = (1.f / (1.f + __expf(-go))) * mask_out[n * DEG + d];
        s_out[grp][d] = so; l_out[grp][d] = lo;
    } else if (lu == 2 * DEG) {
        p_loop[grp] = (1.f / (1.f + __expf(-gloop[n]))) * mask_loop[n];
    }
    __syncthreads();

    const float4* XVin4   = reinterpret_cast<const float4*>(XVin);
    const float4* XVout4  = reinterpret_cast<const float4*>(XVout);
    const float4* XVloop4 = reinterpret_cast<const float4*>(XVloop);
    const float4* bin4    = reinterpret_cast<const float4*>(b_in);
    const float4* bout4   = reinterpret_cast<const float4*>(b_out);

    float pl = p_loop[grp];
    float4 h = XVloop4[(size_t)n * U4 + lu];
    float4 acc = make_float4(pl * h.x, pl * h.y, pl * h.z, pl * h.w);

#pragma unroll
    for (int d = 0; d < DEG; d++) {
        float p = p_in[grp][d];
        float4 v = XVin4[(size_t)s_in[grp][d] * U4 + lu];
        float4 bb = bin4[(size_t)l_in[grp][d] * U4 + lu];
        acc.x = fmaf(p, v.x + bb.x, acc.x);
        acc.y = fmaf(p, v.y + bb.y, acc.y);
        acc.z = fmaf(p, v.z + bb.z, acc.z);
        acc.w = fmaf(p, v.w + bb.w, acc.w);
        p = p_out[grp][d];
        v = XVout4[(size_t)s_out[grp][d] * U4 + lu];
        bb = bout4[(size_t)l_out[grp][d] * U4 + lu];
        acc.x = fmaf(p, v.x + bb.x, acc.x);
        acc.y = fmaf(p, v.y + bb.y, acc.y);
        acc.z = fmaf(p, v.z + bb.z, acc.z);
        acc.w = fmaf(p, v.w + bb.w, acc.w);
    }
    int b = n / T_DIM, t = n % T_DIM;
    float sm = sent_mask[t * B_DIM + b];
    acc.x = fmaxf(acc.x, 0.f) * sm;
    acc.y = fmaxf(acc.y, 0.f) * sm;
    acc.z = fmaxf(acc.z, 0.f) * sm;
    acc.w = fmaxf(acc.w, 0.f) * sm;
    size_t oidx = tb_layout ? ((size_t)t * B_DIM + b) * U4 + lu
                            : (size_t)n * U4 + lu;
    reinterpret_cast<float4*>(Y)[oidx] = acc;
    if (Ytf)
        reinterpret_cast<float4*>(Ytf)[(size_t)n * U4 + lu] = cvt4(acc);
}

// ---------------------------------------------------------------------------
// 4) enc[b] from membank layout
// ---------------------------------------------------------------------------
__global__ void enc_k(const float* __restrict__ MB,
                      const float* __restrict__ sent_mask,
                      float* __restrict__ enc)
{
    int b = blockIdx.x;
    int u = threadIdx.x;  // 0..63
    const float4* M4 = reinterpret_cast<const float4*>(MB);
    float4 s = make_float4(0.f, 0.f, 0.f, 0.f);
#pragma unroll 4
    for (int t = 0; t < T_DIM; t++) {
        float4 v = M4[((size_t)t * B_DIM + b) * U4 + u];
        s.x += v.x; s.y += v.y; s.z += v.z; s.w += v.w;
    }
    __shared__ float ms;
    if (u == 0) {
        float m = 0.f;
        for (int t = 0; t < T_DIM; t++) m += sent_mask[t * B_DIM + b];
        ms = m;
    }
    __syncthreads();
    float inv = 1.f / ms;
    s.x *= inv; s.y *= inv; s.z *= inv; s.w *= inv;
    reinterpret_cast<float4*>(enc)[b * U4 + u] = s;
}

// ---------------------------------------------------------------------------
// 5) h_all[k,b,w] = sum_u enc[b,u] * H[k,u,w]
// ---------------------------------------------------------------------------
__global__ void hall_k(const float* __restrict__ enc,
                       const float* __restrict__ H,
                       float* __restrict__ out)
{
    int k = blockIdx.y, b = blockIdx.x, w = threadIdx.x;
    __shared__ float es[U_DIM];
    es[w] = enc[b * U_DIM + w];
    __syncthreads();
    const float* Hk = H + (size_t)k * U_DIM * U_DIM;
    float acc = 0.f;
#pragma unroll 8
    for (int u = 0; u < U_DIM; u++)
        acc = fmaf(es[u], Hk[u * U_DIM + w], acc);
    out[((size_t)k * B_DIM + b) * U_DIM + w] = acc;
}

// ---------------------------------------------------------------------------
// Launch
// ---------------------------------------------------------------------------
extern "C" void kernel_launch(void* const* d_in, const int* in_sizes, int n_in,
                              void* d_out, int out_size)
{
    const int*   src       = (const int*)  d_in[0];
    const int*   arc_in    = (const int*)  d_in[1];
    const int*   arc_out   = (const int*)  d_in[2];
    const int*   lab_in    = (const int*)  d_in[3];
    const int*   lab_out   = (const int*)  d_in[4];
    const float* mask_in   = (const float*)d_in[5];
    const float* mask_out  = (const float*)d_in[6];
    const float* mask_loop = (const float*)d_in[7];
    const float* sent_mask = (const float*)d_in[8];
    const float* emb       = (const float*)d_in[9];
    const float* V_in      = (const float*)d_in[10];
    const float* b_in      = (const float*)d_in[11];
    const float* Vg_in     = (const float*)d_in[12];
    const float* bg_in     = (const float*)d_in[13];
    const float* V_out     = (const float*)d_in[14];
    const float* b_out     = (const float*)d_in[15];
    const float* Vg_out    = (const float*)d_in[16];
    const float* bg_out    = (const float*)d_in[17];
    const float* W_loop    = (const float*)d_in[18];
    const float* Wg_loop   = (const float*)d_in[19];
    const float* H         = (const float*)d_in[20];
    float* out = (float*)d_out;

    float *pX0, *pX1, *pXtf, *pWtf, *pXVin, *pXVout, *pXVloop;
    float *pgin, *pgout, *pgloop, *penc;
    cudaGetSymbolAddress((void**)&pX0,     g_X0);
    cudaGetSymbolAddress((void**)&pX1,     g_X1);
    cudaGetSymbolAddress((void**)&pXtf,    g_Xtf);
    cudaGetSymbolAddress((void**)&pWtf,    g_Wtf);
    cudaGetSymbolAddress((void**)&pXVin,   g_XVin);
    cudaGetSymbolAddress((void**)&pXVout,  g_XVout);
    cudaGetSymbolAddress((void**)&pXVloop, g_XVloop);
    cudaGetSymbolAddress((void**)&pgin,    g_gin);
    cudaGetSymbolAddress((void**)&pgout,   g_gout);
    cudaGetSymbolAddress((void**)&pgloop,  g_gloop);
    cudaGetSymbolAddress((void**)&penc,    g_enc);

    cudaFuncSetAttribute(gemm_gate_k,
                         cudaFuncAttributeMaxDynamicSharedMemorySize, SMEM_DYN);

    float* memOut = out + 4 * B_DIM * U_DIM;   // membank region of d_out

    cvtw_k<<<L_LAYERS * 3 * WSZ / 4 / 256, 256>>>(V_in, V_out, W_loop, pWtf);
    embed_k<<<BT / 4, 256>>>(src, emb, pX0, pXtf);

    float* Xcur = pX0;
    for (int l = 0; l < L_LAYERS; l++) {
        const size_t gOff  = (size_t)l * U_DIM;
        const size_t bOff  = (size_t)l * NL_LAB * U_DIM;
        const size_t bgOff = (size_t)l * NL_LAB;
        const int last = (l == L_LAYERS - 1);

        gemm_gate_k<<<TOTAL_BLOCKS, GTHREADS, SMEM_DYN>>>(
            pXtf, pWtf + (size_t)l * 3 * WSZ,
            pXVin, pXVout, pXVloop,
            Xcur,
            Vg_in + gOff, Vg_out + gOff, Wg_loop + gOff,
            pgin, pgout, pgloop);
        agg_k<<<BT / 4, 256>>>(pXVin, pXVout, pXVloop, pgin, pgout, pgloop,
                               arc_in, arc_out, lab_in, lab_out,
                               b_in + bOff, bg_in + bgOff,
                               b_out + bOff, bg_out + bgOff,
                               mask_in, mask_out, mask_loop, sent_mask,
                               last ? memOut : pX1,
                               last ? nullptr : pXtf,
                               last ? 1 : 0);
        Xcur = pX1;
    }

    enc_k<<<B_DIM, 64>>>(memOut, sent_mask, penc);
    hall_k<<<dim3(B_DIM, 4), U_DIM>>>(penc, H, out);
}

// round 11
// speedup vs baseline: 1.2706x; 1.2706x over previous
#include <cuda_runtime.h>
#include <cuda_fp16.h>
#include <cstdint>

// Problem constants
#define L_LAYERS 2
#define U_DIM    256
#define U4       (U_DIM / 4)
#define NL_LAB   64
#define B_DIM    128
#define T_DIM    128
#define DEG      5
#define BT       (B_DIM * T_DIM)          // 16384 nodes
#define E_EDGES  (BT * DEG)               // 81920
#define WSZ      (U_DIM * U_DIM)          // 65536 elems per weight matrix

// ---------------------------------------------------------------------------
// Scratch (device globals — no allocation allowed)
// ---------------------------------------------------------------------------
__device__ float  g_X0[BT * U_DIM];
__device__ float  g_X1[BT * U_DIM];
__device__ __half g_Xh[BT * U_DIM];               // fp16 copy of X (GEMM A)
__device__ __half g_Wh[L_LAYERS * 3 * WSZ];       // fp16 W^T, [l][sel][N][K]
__device__ float  g_XVin[BT * U_DIM];
__device__ float  g_XVout[BT * U_DIM];
__device__ float  g_XVloop[BT * U_DIM];
__device__ float  g_gin[BT];
__device__ float  g_gout[BT];
__device__ float  g_gloop[BT];
__device__ float  g_enc[B_DIM * U_DIM];

// ---------------------------------------------------------------------------
// helpers
// ---------------------------------------------------------------------------
__device__ __forceinline__ uint2 f4toh4(float4 v) {
    __half2 h01 = __floats2half2_rn(v.x, v.y);
    __half2 h23 = __floats2half2_rn(v.z, v.w);
    uint2 r;
    r.x = *reinterpret_cast<uint32_t*>(&h01);
    r.y = *reinterpret_cast<uint32_t*>(&h23);
    return r;
}

__device__ __forceinline__ void mma_f16(float* d, const uint32_t* a,
                                        const uint32_t* b) {
    asm volatile(
        "mma.sync.aligned.m16n8k16.row.col.f32.f16.f16.f32 "
        "{%0,%1,%2,%3}, {%4,%5,%6,%7}, {%8,%9}, {%0,%1,%2,%3};\n"
        : "+f"(d[0]), "+f"(d[1]), "+f"(d[2]), "+f"(d[3])
        : "r"(a[0]), "r"(a[1]), "r"(a[2]), "r"(a[3]), "r"(b[0]), "r"(b[1]));
}

__device__ __forceinline__ void cp16(void* dst, const void* src) {
    uint32_t d = (uint32_t)__cvta_generic_to_shared(dst);
    asm volatile("cp.async.cg.shared.global [%0], [%1], 16;\n"
                 :: "r"(d), "l"(src));
}
#define CP_COMMIT() asm volatile("cp.async.commit_group;\n" ::: "memory")
#define CP_WAIT1()  asm volatile("cp.async.wait_group 1;\n" ::: "memory")
#define CP_WAIT0()  asm volatile("cp.async.wait_group 0;\n" ::: "memory")

// ---------------------------------------------------------------------------
// 0) Weight convert + transpose: Wh[l][sel][n][k] = fp16(W[l][sel][k][n])
//    grid(8,8,6), block(32,32)
// ---------------------------------------------------------------------------
__global__ void cvtwT_k(const float* __restrict__ Vin,
                        const float* __restrict__ Vout,
                        const float* __restrict__ Wloop,
                        __half* __restrict__ out)
{
    __shared__ float ts[32][33];
    int z = blockIdx.z;                  // l*3 + sel
    int l = z / 3, sel = z % 3;
    const float* src = ((sel == 0) ? Vin : (sel == 1) ? Vout : Wloop)
                       + (size_t)l * WSZ;
    __half* dst = out + (size_t)z * WSZ;
    int kk = blockIdx.y * 32 + threadIdx.y;
    int nn = blockIdx.x * 32 + threadIdx.x;
    ts[threadIdx.y][threadIdx.x] = src[(size_t)kk * U_DIM + nn];
    __syncthreads();
    int on = blockIdx.x * 32 + threadIdx.y;
    int ok = blockIdx.y * 32 + threadIdx.x;
    dst[(size_t)on * U_DIM + ok] = __float2half_rn(ts[threadIdx.x][threadIdx.y]);
}

// ---------------------------------------------------------------------------
// 1) Embedding gather: X[n=b*T+t] = emb[src[t,b]]; also fp16 copy.
// ---------------------------------------------------------------------------
__global__ void embed_k(const int* __restrict__ src,
                        const float* __restrict__ emb,
                        float* __restrict__ X,
                        __half* __restrict__ Xh)
{
    int grp = threadIdx.x >> 6;
    int n   = blockIdx.x * 4 + grp;
    int lu  = threadIdx.x & 63;
    int b = n / T_DIM, t = n % T_DIM;
    int tok = src[t * B_DIM + b];
    float4 v = reinterpret_cast<const float4*>(emb)[(size_t)tok * U4 + lu];
    reinterpret_cast<float4*>(X)[(size_t)n * U4 + lu] = v;
    reinterpret_cast<uint2*>(Xh)[(size_t)n * U4 + lu] = f4toh4(v);
}

// ---------------------------------------------------------------------------
// 2) Fused FP16 GEMM + gates. 1D grid of 888 blocks, 512 threads.
//      bid in [0,768): GEMM. x = bid&127 (m-tile), y = bid>>7 in [0,6):
//                      sel=y>>1 picks W/C, (y&1)*128 picks N half.
//                      128x128 tile, BK=32 halves, m16n8k16 fp16 MMA,
//                      3-stage cp.async, 1 barrier/tile, 16 warps (4Mx4N).
//      bid in [768,888): gate GEMVs on fp32 X, grid-stride.
// ---------------------------------------------------------------------------
#define GBM 128
#define GBN 128
#define GBK 32                 // halves per k-tile
#define NT  (U_DIM / GBK)      // 8 k-tiles
#define GTHREADS 512
#define GEMM_BLOCKS 768
#define GATE_BLOCKS 120
#define TOTAL_BLOCKS (GEMM_BLOCKS + GATE_BLOCKS)
#define HPITCH 40              // halves per smem row (80B = 20 banks; conflict-free)
#define A_STAGE_H (GBM * HPITCH)     // 5120 halves
#define B_STAGE_H (GBN * HPITCH)     // 5120 halves
#define SMEM_DYN  (3 * (A_STAGE_H + B_STAGE_H) * 2)   // 61,440 B

__global__ __launch_bounds__(GTHREADS, 2)
void gemm_gate_k(const __half* __restrict__ Ah,
                 const __half* __restrict__ Wh,   // [3][N][K] this layer
                 float* __restrict__ C0, float* __restrict__ C1,
                 float* __restrict__ C2,
                 const float* __restrict__ Aorig,
                 const float* __restrict__ vgin,
                 const float* __restrict__ vgout,
                 const float* __restrict__ wgl,
                 float* __restrict__ gin, float* __restrict__ gout,
                 float* __restrict__ gloop)
{
    const int bid = blockIdx.x;

    // ---------------- gate slice (grid-stride) ----------------
    if (bid >= GEMM_BLOCKS) {
        int gblk = bid - GEMM_BLOCKS;
        int warp = threadIdx.x >> 5;
        int lane = threadIdx.x & 31;
        const float4* v0 = reinterpret_cast<const float4*>(vgin);
        const float4* v1 = reinterpret_cast<const float4*>(vgout);
        const float4* v2 = reinterpret_cast<const float4*>(wgl);
        const int stride = GATE_BLOCKS * 16;
#pragma unroll 1
        for (int n = gblk * 16 + warp; n < BT; n += stride) {
            const float4* xr =
                reinterpret_cast<const float4*>(Aorig + (size_t)n * U_DIM);
            float s0 = 0.f, s1 = 0.f, s2 = 0.f;
#pragma unroll
            for (int k = lane; k < U4; k += 32) {
                float4 x = xr[k];
                float4 a = v0[k], b = v1[k], c = v2[k];
                s0 += x.x * a.x + x.y * a.y + x.z * a.z + x.w * a.w;
                s1 += x.x * b.x + x.y * b.y + x.z * b.z + x.w * b.w;
                s2 += x.x * c.x + x.y * c.y + x.z * c.z + x.w * c.w;
            }
#pragma unroll
            for (int off = 16; off > 0; off >>= 1) {
                s0 += __shfl_down_sync(0xffffffffu, s0, off);
                s1 += __shfl_down_sync(0xffffffffu, s1, off);
                s2 += __shfl_down_sync(0xffffffffu, s2, off);
            }
            if (lane == 0) { gin[n] = s0; gout[n] = s1; gloop[n] = s2; }
        }
        return;
    }

    // ---------------- GEMM slice ----------------
    const int xb      = bid & 127;
    const int yb      = bid >> 7;              // 0..5
    const int sel     = yb >> 1;
    const int colbase = (yb & 1) * GBN;
    const __half* __restrict__ W = Wh + (size_t)sel * WSZ;   // [N][K]
    float* __restrict__ C        = (sel == 0) ? C0 : ((sel == 1) ? C1 : C2);
    const int mbase = xb * GBM;

    extern __shared__ __align__(16) __half hsm[];
    __half* Asm = hsm;                         // 3 stages of [GBM][HPITCH]
    __half* Bsm = hsm + 3 * A_STAGE_H;         // 3 stages of [GBN][HPITCH]

    const int tid  = threadIdx.x;
    const int lane = tid & 31;
    const int warp = tid >> 5;
    const int wm   = (warp & 3) * 32;          // warp M offset
    const int wn   = (warp >> 2) * 32;         // warp N offset
    const int g    = lane >> 2;                // 0..7
    const int t    = lane & 3;                 // 0..3

    // cp.async: one 16B (8 halves) per thread per operand per tile
    const int ldRow = tid >> 2;                // 0..127
    const int ldH   = (tid & 3) * 8;           // 0,8,16,24 halves

    const __half* Abase = Ah + (size_t)(mbase + ldRow) * U_DIM + ldH;
    const __half* Wbase = W + (size_t)(colbase + ldRow) * U_DIM + ldH;
    __half* AsmRow = Asm + ldRow * HPITCH + ldH;
    __half* BsmRow = Bsm + ldRow * HPITCH + ldH;

    float acc[2][4][4];
#pragma unroll
    for (int mi = 0; mi < 2; mi++)
#pragma unroll
        for (int ni = 0; ni < 4; ni++)
#pragma unroll
            for (int c = 0; c < 4; c++) acc[mi][ni][c] = 0.f;

    // prologue: tiles 0 and 1 into stages 0 and 1
    cp16(AsmRow,             Abase);
    cp16(BsmRow,             Wbase);
    CP_COMMIT();
    cp16(AsmRow + A_STAGE_H, Abase + GBK);
    cp16(BsmRow + B_STAGE_H, Wbase + GBK);
    CP_COMMIT();

#pragma unroll 1
    for (int tile = 0; tile < NT; tile++) {
        if (tile < NT - 1) { CP_WAIT1(); } else { CP_WAIT0(); }
        __syncthreads();   // tile data visible; stage (tile+2)%3 free

        int nxt = tile + 2;
        if (nxt < NT) {
            int s  = nxt % 3;
            int k0 = nxt * GBK;
            cp16(AsmRow + s * A_STAGE_H, Abase + k0);
            cp16(BsmRow + s * B_STAGE_H, Wbase + k0);
            CP_COMMIT();
        }

        const int st = tile % 3;
        const __half* As = Asm + st * A_STAGE_H;
        const __half* Bs = Bsm + st * B_STAGE_H;
#pragma unroll
        for (int ks = 0; ks < GBK; ks += 16) {
            uint32_t afr[2][4];
#pragma unroll
            for (int mi = 0; mi < 2; mi++) {
                int m0 = wm + mi * 16;
                const __half* r0 = As + (m0 + g) * HPITCH + ks + 2 * t;
                const __half* r1 = As + (m0 + g + 8) * HPITCH + ks + 2 * t;
                afr[mi][0] = *reinterpret_cast<const uint32_t*>(r0);
                afr[mi][1] = *reinterpret_cast<const uint32_t*>(r1);
                afr[mi][2] = *reinterpret_cast<const uint32_t*>(r0 + 8);
                afr[mi][3] = *reinterpret_cast<const uint32_t*>(r1 + 8);
            }
            uint32_t bfr[4][2];
#pragma unroll
            for (int ni = 0; ni < 4; ni++) {
                int n0 = wn + ni * 8 + g;
                const __half* rb = Bs + n0 * HPITCH + ks + 2 * t;
                bfr[ni][0] = *reinterpret_cast<const uint32_t*>(rb);
                bfr[ni][1] = *reinterpret_cast<const uint32_t*>(rb + 8);
            }
#pragma unroll
            for (int mi = 0; mi < 2; mi++)
#pragma unroll
                for (int ni = 0; ni < 4; ni++)
                    mma_f16(acc[mi][ni], afr[mi], bfr[ni]);
        }
    }

    // epilogue (C fragment layout identical to tf32 path)
#pragma unroll
    for (int mi = 0; mi < 2; mi++) {
#pragma unroll
        for (int ni = 0; ni < 4; ni++) {
            int row = mbase + wm + mi * 16 + g;
            int col = colbase + wn + ni * 8 + 2 * t;
            float2 v0 = make_float2(acc[mi][ni][0], acc[mi][ni][1]);
            float2 v1 = make_float2(acc[mi][ni][2], acc[mi][ni][3]);
            *reinterpret_cast<float2*>(&C[(size_t)row * U_DIM + col])       = v0;
            *reinterpret_cast<float2*>(&C[(size_t)(row + 8) * U_DIM + col]) = v1;
        }
    }
}

// ---------------------------------------------------------------------------
// 3) Edge aggregation, float4: 64 threads/node, 4 nodes/block.
//    Yh != nullptr -> also write fp16 copy (next layer's GEMM A).
// ---------------------------------------------------------------------------
__global__ __launch_bounds__(256)
void agg_k(const float* __restrict__ XVin,
           const float* __restrict__ XVout,
           const float* __restrict__ XVloop,
           const float* __restrict__ gin,
           const float* __restrict__ gout,
           const float* __restrict__ gloop,
           const int* __restrict__ arc_in,
           const int* __restrict__ arc_out,
           const int* __restrict__ lab_in,
           const int* __restrict__ lab_out,
           const float* __restrict__ b_in,
           const float* __restrict__ bg_in,
           const float* __restrict__ b_out,
           const float* __restrict__ bg_out,
           const float* __restrict__ mask_in,
           const float* __restrict__ mask_out,
           const float* __restrict__ mask_loop,
           const float* __restrict__ sent_mask,
           float* __restrict__ Y, __half* __restrict__ Yh, int tb_layout)
{
    int grp = threadIdx.x >> 6;
    int n   = blockIdx.x * 4 + grp;
    int lu  = threadIdx.x & 63;

    __shared__ float p_in[4][DEG], p_out[4][DEG], p_loop[4];
    __shared__ int   s_in[4][DEG], s_out[4][DEG], l_in[4][DEG], l_out[4][DEG];

    if (lu < DEG) {
        int d = lu, e = n * DEG + d;
        int si = arc_in[e] * T_DIM + arc_in[E_EDGES + e];
        int li = lab_in[e];
        float gi = gin[si] + bg_in[li];
        p_in[grp][d] = (1.f / (1.f + __expf(-gi))) * mask_in[n * DEG + d];
        s_in[grp][d] = si; l_in[grp][d] = li;
    } else if (lu < 2 * DEG) {
        int d = lu - DEG, e = n * DEG + d;
        int so = arc_out[e] * T_DIM + arc_out[E_EDGES + e];
        int lo = lab_out[e];
        float go = gout[so] + bg_out[lo];
        p_out[grp][d] = (1.f / (1.f + __expf(-go))) * mask_out[n * DEG + d];
        s_out[grp][d] = so; l_out[grp][d] = lo;
    } else if (lu == 2 * DEG) {
        p_loop[grp] = (1.f / (1.f + __expf(-gloop[n]))) * mask_loop[n];
    }
    __syncthreads();

    const float4* XVin4   = reinterpret_cast<const float4*>(XVin);
    const float4* XVout4  = reinterpret_cast<const float4*>(XVout);
    const float4* XVloop4 = reinterpret_cast<const float4*>(XVloop);
    const float4* bin4    = reinterpret_cast<const float4*>(b_in);
    const float4* bout4   = reinterpret_cast<const float4*>(b_out);

    float pl = p_loop[grp];
    float4 h = XVloop4[(size_t)n * U4 + lu];
    float4 acc = make_float4(pl * h.x, pl * h.y, pl * h.z, pl * h.w);

#pragma unroll
    for (int d = 0; d < DEG; d++) {
        float p = p_in[grp][d];
        float4 v = XVin4[(size_t)s_in[grp][d] * U4 + lu];
        float4 bb = bin4[(size_t)l_in[grp][d] * U4 + lu];
        acc.x = fmaf(p, v.x + bb.x, acc.x);
        acc.y = fmaf(p, v.y + bb.y, acc.y);
        acc.z = fmaf(p, v.z + bb.z, acc.z);
        acc.w = fmaf(p, v.w + bb.w, acc.w);
        p = p_out[grp][d];
        v = XVout4[(size_t)s_out[grp][d] * U4 + lu];
        bb = bout4[(size_t)l_out[grp][d] * U4 + lu];
        acc.x = fmaf(p, v.x + bb.x, acc.x);
        acc.y = fmaf(p, v.y + bb.y, acc.y);
        acc.z = fmaf(p, v.z + bb.z, acc.z);
        acc.w = fmaf(p, v.w + bb.w, acc.w);
    }
    int b = n / T_DIM, t = n % T_DIM;
    float sm = sent_mask[t * B_DIM + b];
    acc.x = fmaxf(acc.x, 0.f) * sm;
    acc.y = fmaxf(acc.y, 0.f) * sm;
    acc.z = fmaxf(acc.z, 0.f) * sm;
    acc.w = fmaxf(acc.w, 0.f) * sm;
    size_t oidx = tb_layout ? ((size_t)t * B_DIM + b) * U4 + lu
                            : (size_t)n * U4 + lu;
    reinterpret_cast<float4*>(Y)[oidx] = acc;
    if (Yh)
        reinterpret_cast<uint2*>(Yh)[(size_t)n * U4 + lu] = f4toh4(acc);
}

// ---------------------------------------------------------------------------
// 4) enc[b] from membank layout
// ---------------------------------------------------------------------------
__global__ void enc_k(const float* __restrict__ MB,
                      const float* __restrict__ sent_mask,
                      float* __restrict__ enc)
{
    int b = blockIdx.x;
    int u = threadIdx.x;  // 0..63
    const float4* M4 = reinterpret_cast<const float4*>(MB);
    float4 s = make_float4(0.f, 0.f, 0.f, 0.f);
#pragma unroll 4
    for (int t = 0; t < T_DIM; t++) {
        float4 v = M4[((size_t)t * B_DIM + b) * U4 + u];
        s.x += v.x; s.y += v.y; s.z += v.z; s.w += v.w;
    }
    __shared__ float ms;
    if (u == 0) {
        float m = 0.f;
        for (int t = 0; t < T_DIM; t++) m += sent_mask[t * B_DIM + b];
        ms = m;
    }
    __syncthreads();
    float inv = 1.f / ms;
    s.x *= inv; s.y *= inv; s.z *= inv; s.w *= inv;
    reinterpret_cast<float4*>(enc)[b * U4 + u] = s;
}

// ---------------------------------------------------------------------------
// 5) h_all[k,b,w] = sum_u enc[b,u] * H[k,u,w]
// ---------------------------------------------------------------------------
__global__ void hall_k(const float* __restrict__ enc,
                       const float* __restrict__ H,
                       float* __restrict__ out)
{
    int k = blockIdx.y, b = blockIdx.x, w = threadIdx.x;
    __shared__ float es[U_DIM];
    es[w] = enc[b * U_DIM + w];
    __syncthreads();
    const float* Hk = H + (size_t)k * U_DIM * U_DIM;
    float acc = 0.f;
#pragma unroll 8
    for (int u = 0; u < U_DIM; u++)
        acc = fmaf(es[u], Hk[u * U_DIM + w], acc);
    out[((size_t)k * B_DIM + b) * U_DIM + w] = acc;
}

// ---------------------------------------------------------------------------
// Launch
// ---------------------------------------------------------------------------
extern "C" void kernel_launch(void* const* d_in, const int* in_sizes, int n_in,
                              void* d_out, int out_size)
{
    const int*   src       = (const int*)  d_in[0];
    const int*   arc_in    = (const int*)  d_in[1];
    const int*   arc_out   = (const int*)  d_in[2];
    const int*   lab_in    = (const int*)  d_in[3];
    const int*   lab_out   = (const int*)  d_in[4];
    const float* mask_in   = (const float*)d_in[5];
    const float* mask_out  = (const float*)d_in[6];
    const float* mask_loop = (const float*)d_in[7];
    const float* sent_mask = (const float*)d_in[8];
    const float* emb       = (const float*)d_in[9];
    const float* V_in      = (const float*)d_in[10];
    const float* b_in      = (const float*)d_in[11];
    const float* Vg_in     = (const float*)d_in[12];
    const float* bg_in     = (const float*)d_in[13];
    const float* V_out     = (const float*)d_in[14];
    const float* b_out     = (const float*)d_in[15];
    const float* Vg_out    = (const float*)d_in[16];
    const float* bg_out    = (const float*)d_in[17];
    const float* W_loop    = (const float*)d_in[18];
    const float* Wg_loop   = (const float*)d_in[19];
    const float* H         = (const float*)d_in[20];
    float* out = (float*)d_out;

    float *pX0, *pX1, *pXVin, *pXVout, *pXVloop, *pgin, *pgout, *pgloop, *penc;
    __half *pXh, *pWh;
    cudaGetSymbolAddress((void**)&pX0,     g_X0);
    cudaGetSymbolAddress((void**)&pX1,     g_X1);
    cudaGetSymbolAddress((void**)&pXh,     g_Xh);
    cudaGetSymbolAddress((void**)&pWh,     g_Wh);
    cudaGetSymbolAddress((void**)&pXVin,   g_XVin);
    cudaGetSymbolAddress((void**)&pXVout,  g_XVout);
    cudaGetSymbolAddress((void**)&pXVloop, g_XVloop);
    cudaGetSymbolAddress((void**)&pgin,    g_gin);
    cudaGetSymbolAddress((void**)&pgout,   g_gout);
    cudaGetSymbolAddress((void**)&pgloop,  g_gloop);
    cudaGetSymbolAddress((void**)&penc,    g_enc);

    cudaFuncSetAttribute(gemm_gate_k,
                         cudaFuncAttributeMaxDynamicSharedMemorySize, SMEM_DYN);

    float* memOut = out + 4 * B_DIM * U_DIM;   // membank region of d_out

    cvtwT_k<<<dim3(8, 8, 6), dim3(32, 32)>>>(V_in, V_out, W_loop, pWh);
    embed_k<<<BT / 4, 256>>>(src, emb, pX0, pXh);

    float* Xcur = pX0;
    for (int l = 0; l < L_LAYERS; l++) {
        const size_t gOff  = (size_t)l * U_DIM;
        const size_t bOff  = (size_t)l * NL_LAB * U_DIM;
        const size_t bgOff = (size_t)l * NL_LAB;
        const int last = (l == L_LAYERS - 1);

        gemm_gate_k<<<TOTAL_BLOCKS, GTHREADS, SMEM_DYN>>>(
            pXh, pWh + (size_t)l * 3 * WSZ,
            pXVin, pXVout, pXVloop,
            Xcur,
            Vg_in + gOff, Vg_out + gOff, Wg_loop + gOff,
            pgin, pgout, pgloop);
        agg_k<<<BT / 4, 256>>>(pXVin, pXVout, pXVloop, pgin, pgout, pgloop,
                               arc_in, arc_out, lab_in, lab_out,
                               b_in + bOff, bg_in + bgOff,
                               b_out + bOff, bg_out + bgOff,
                               mask_in, mask_out, mask_loop, sent_mask,
                               last ? memOut : pX1,
                               last ? nullptr : pXh,
                               last ? 1 : 0);
        Xcur = pX1;
    }

    enc_k<<<B_DIM, 64>>>(memOut, sent_mask, penc);
    hall_k<<<dim3(B_DIM, 4), U_DIM>>>(penc, H, out);
}

// round 12
// speedup vs baseline: 1.3467x; 1.0599x over previous
#include <cuda_runtime.h>
#include <cuda_fp16.h>
#include <cstdint>

// Problem constants
#define L_LAYERS 2
#define U_DIM    256
#define U4       (U_DIM / 4)
#define NL_LAB   64
#define B_DIM    128
#define T_DIM    128
#define DEG      5
#define BT       (B_DIM * T_DIM)          // 16384 nodes
#define E_EDGES  (BT * DEG)               // 81920
#define WSZ      (U_DIM * U_DIM)          // 65536 elems per weight matrix

// ---------------------------------------------------------------------------
// Scratch (device globals — no allocation allowed)
// ---------------------------------------------------------------------------
__device__ float  g_X0[BT * U_DIM];
__device__ float  g_X1[BT * U_DIM];
__device__ __half g_Xh[BT * U_DIM];               // fp16 copy of X (GEMM A)
__device__ __half g_Wh[L_LAYERS * 3 * WSZ];       // fp16 W^T, [l][sel][N][K]
__device__ __half g_XVin[BT * U_DIM];             // fp16 GEMM outputs
__device__ __half g_XVout[BT * U_DIM];
__device__ __half g_XVloop[BT * U_DIM];
__device__ float  g_gin[BT];
__device__ float  g_gout[BT];
__device__ float  g_gloop[BT];
__device__ float  g_enc[B_DIM * U_DIM];

// ---------------------------------------------------------------------------
// helpers
// ---------------------------------------------------------------------------
__device__ __forceinline__ uint2 f4toh4(float4 v) {
    __half2 h01 = __floats2half2_rn(v.x, v.y);
    __half2 h23 = __floats2half2_rn(v.z, v.w);
    uint2 r;
    r.x = *reinterpret_cast<uint32_t*>(&h01);
    r.y = *reinterpret_cast<uint32_t*>(&h23);
    return r;
}

__device__ __forceinline__ float4 h4tof4(uint2 u) {
    __half2 h01 = *reinterpret_cast<__half2*>(&u.x);
    __half2 h23 = *reinterpret_cast<__half2*>(&u.y);
    float2 f01 = __half22float2(h01);
    float2 f23 = __half22float2(h23);
    return make_float4(f01.x, f01.y, f23.x, f23.y);
}

__device__ __forceinline__ void mma_f16(float* d, const uint32_t* a,
                                        const uint32_t* b) {
    asm volatile(
        "mma.sync.aligned.m16n8k16.row.col.f32.f16.f16.f32 "
        "{%0,%1,%2,%3}, {%4,%5,%6,%7}, {%8,%9}, {%0,%1,%2,%3};\n"
        : "+f"(d[0]), "+f"(d[1]), "+f"(d[2]), "+f"(d[3])
        : "r"(a[0]), "r"(a[1]), "r"(a[2]), "r"(a[3]), "r"(b[0]), "r"(b[1]));
}

__device__ __forceinline__ void cp16(void* dst, const void* src) {
    uint32_t d = (uint32_t)__cvta_generic_to_shared(dst);
    asm volatile("cp.async.cg.shared.global [%0], [%1], 16;\n"
                 :: "r"(d), "l"(src));
}
#define CP_COMMIT() asm volatile("cp.async.commit_group;\n" ::: "memory")
#define CP_WAIT1()  asm volatile("cp.async.wait_group 1;\n" ::: "memory")
#define CP_WAIT0()  asm volatile("cp.async.wait_group 0;\n" ::: "memory")

// ---------------------------------------------------------------------------
// 0) Weight convert + transpose: Wh[l][sel][n][k] = fp16(W[l][sel][k][n])
// ---------------------------------------------------------------------------
__global__ void cvtwT_k(const float* __restrict__ Vin,
                        const float* __restrict__ Vout,
                        const float* __restrict__ Wloop,
                        __half* __restrict__ out)
{
    __shared__ float ts[32][33];
    int z = blockIdx.z;                  // l*3 + sel
    int l = z / 3, sel = z % 3;
    const float* src = ((sel == 0) ? Vin : (sel == 1) ? Vout : Wloop)
                       + (size_t)l * WSZ;
    __half* dst = out + (size_t)z * WSZ;
    int kk = blockIdx.y * 32 + threadIdx.y;
    int nn = blockIdx.x * 32 + threadIdx.x;
    ts[threadIdx.y][threadIdx.x] = src[(size_t)kk * U_DIM + nn];
    __syncthreads();
    int on = blockIdx.x * 32 + threadIdx.y;
    int ok = blockIdx.y * 32 + threadIdx.x;
    dst[(size_t)on * U_DIM + ok] = __float2half_rn(ts[threadIdx.x][threadIdx.y]);
}

// ---------------------------------------------------------------------------
// 1) Embedding gather: X[n=b*T+t] = emb[src[t,b]]; also fp16 copy.
// ---------------------------------------------------------------------------
__global__ void embed_k(const int* __restrict__ src,
                        const float* __restrict__ emb,
                        float* __restrict__ X,
                        __half* __restrict__ Xh)
{
    int grp = threadIdx.x >> 6;
    int n   = blockIdx.x * 4 + grp;
    int lu  = threadIdx.x & 63;
    int b = n / T_DIM, t = n % T_DIM;
    int tok = src[t * B_DIM + b];
    float4 v = reinterpret_cast<const float4*>(emb)[(size_t)tok * U4 + lu];
    reinterpret_cast<float4*>(X)[(size_t)n * U4 + lu] = v;
    reinterpret_cast<uint2*>(Xh)[(size_t)n * U4 + lu] = f4toh4(v);
}

// ---------------------------------------------------------------------------
// 2) Fused FP16 GEMM + gates. 1D grid of 888 blocks, 512 threads.
//      bid in [0,768): GEMM (fp16 in, fp32 accum, fp16 C out).
//      bid in [768,888): gate GEMVs on fp32 X, grid-stride.
// ---------------------------------------------------------------------------
#define GBM 128
#define GBN 128
#define GBK 32                 // halves per k-tile
#define NT  (U_DIM / GBK)      // 8 k-tiles
#define GTHREADS 512
#define GEMM_BLOCKS 768
#define GATE_BLOCKS 120
#define TOTAL_BLOCKS (GEMM_BLOCKS + GATE_BLOCKS)
#define HPITCH 40              // halves per smem row
#define A_STAGE_H (GBM * HPITCH)     // 5120 halves
#define B_STAGE_H (GBN * HPITCH)     // 5120 halves
#define SMEM_DYN  (3 * (A_STAGE_H + B_STAGE_H) * 2)   // 61,440 B

__global__ __launch_bounds__(GTHREADS, 2)
void gemm_gate_k(const __half* __restrict__ Ah,
                 const __half* __restrict__ Wh,   // [3][N][K] this layer
                 __half* __restrict__ C0, __half* __restrict__ C1,
                 __half* __restrict__ C2,
                 const float* __restrict__ Aorig,
                 const float* __restrict__ vgin,
                 const float* __restrict__ vgout,
                 const float* __restrict__ wgl,
                 float* __restrict__ gin, float* __restrict__ gout,
                 float* __restrict__ gloop)
{
    const int bid = blockIdx.x;

    // ---------------- gate slice (grid-stride) ----------------
    if (bid >= GEMM_BLOCKS) {
        int gblk = bid - GEMM_BLOCKS;
        int warp = threadIdx.x >> 5;
        int lane = threadIdx.x & 31;
        const float4* v0 = reinterpret_cast<const float4*>(vgin);
        const float4* v1 = reinterpret_cast<const float4*>(vgout);
        const float4* v2 = reinterpret_cast<const float4*>(wgl);
        const int stride = GATE_BLOCKS * 16;
#pragma unroll 1
        for (int n = gblk * 16 + warp; n < BT; n += stride) {
            const float4* xr =
                reinterpret_cast<const float4*>(Aorig + (size_t)n * U_DIM);
            float s0 = 0.f, s1 = 0.f, s2 = 0.f;
#pragma unroll
            for (int k = lane; k < U4; k += 32) {
                float4 x = xr[k];
                float4 a = v0[k], b = v1[k], c = v2[k];
                s0 += x.x * a.x + x.y * a.y + x.z * a.z + x.w * a.w;
                s1 += x.x * b.x + x.y * b.y + x.z * b.z + x.w * b.w;
                s2 += x.x * c.x + x.y * c.y + x.z * c.z + x.w * c.w;
            }
#pragma unroll
            for (int off = 16; off > 0; off >>= 1) {
                s0 += __shfl_down_sync(0xffffffffu, s0, off);
                s1 += __shfl_down_sync(0xffffffffu, s1, off);
                s2 += __shfl_down_sync(0xffffffffu, s2, off);
            }
            if (lane == 0) { gin[n] = s0; gout[n] = s1; gloop[n] = s2; }
        }
        return;
    }

    // ---------------- GEMM slice ----------------
    const int xb      = bid & 127;
    const int yb      = bid >> 7;              // 0..5
    const int sel     = yb >> 1;
    const int colbase = (yb & 1) * GBN;
    const __half* __restrict__ W = Wh + (size_t)sel * WSZ;   // [N][K]
    __half* __restrict__ C       = (sel == 0) ? C0 : ((sel == 1) ? C1 : C2);
    const int mbase = xb * GBM;

    extern __shared__ __align__(16) __half hsm[];
    __half* Asm = hsm;                         // 3 stages of [GBM][HPITCH]
    __half* Bsm = hsm + 3 * A_STAGE_H;         // 3 stages of [GBN][HPITCH]

    const int tid  = threadIdx.x;
    const int lane = tid & 31;
    const int warp = tid >> 5;
    const int wm   = (warp & 3) * 32;          // warp M offset
    const int wn   = (warp >> 2) * 32;         // warp N offset
    const int g    = lane >> 2;                // 0..7
    const int t    = lane & 3;                 // 0..3

    // cp.async: one 16B (8 halves) per thread per operand per tile
    const int ldRow = tid >> 2;                // 0..127
    const int ldH   = (tid & 3) * 8;           // 0,8,16,24 halves

    const __half* Abase = Ah + (size_t)(mbase + ldRow) * U_DIM + ldH;
    const __half* Wbase = W + (size_t)(colbase + ldRow) * U_DIM + ldH;
    __half* AsmRow = Asm + ldRow * HPITCH + ldH;
    __half* BsmRow = Bsm + ldRow * HPITCH + ldH;

    float acc[2][4][4];
#pragma unroll
    for (int mi = 0; mi < 2; mi++)
#pragma unroll
        for (int ni = 0; ni < 4; ni++)
#pragma unroll
            for (int c = 0; c < 4; c++) acc[mi][ni][c] = 0.f;

    // prologue: tiles 0 and 1 into stages 0 and 1
    cp16(AsmRow,             Abase);
    cp16(BsmRow,             Wbase);
    CP_COMMIT();
    cp16(AsmRow + A_STAGE_H, Abase + GBK);
    cp16(BsmRow + B_STAGE_H, Wbase + GBK);
    CP_COMMIT();

#pragma unroll 1
    for (int tile = 0; tile < NT; tile++) {
        if (tile < NT - 1) { CP_WAIT1(); } else { CP_WAIT0(); }
        __syncthreads();   // tile data visible; stage (tile+2)%3 free

        int nxt = tile + 2;
        if (nxt < NT) {
            int s  = nxt % 3;
            int k0 = nxt * GBK;
            cp16(AsmRow + s * A_STAGE_H, Abase + k0);
            cp16(BsmRow + s * B_STAGE_H, Wbase + k0);
            CP_COMMIT();
        }

        const int st = tile % 3;
        const __half* As = Asm + st * A_STAGE_H;
        const __half* Bs = Bsm + st * B_STAGE_H;
#pragma unroll
        for (int ks = 0; ks < GBK; ks += 16) {
            uint32_t afr[2][4];
#pragma unroll
            for (int mi = 0; mi < 2; mi++) {
                int m0 = wm + mi * 16;
                const __half* r0 = As + (m0 + g) * HPITCH + ks + 2 * t;
                const __half* r1 = As + (m0 + g + 8) * HPITCH + ks + 2 * t;
                afr[mi][0] = *reinterpret_cast<const uint32_t*>(r0);
                afr[mi][1] = *reinterpret_cast<const uint32_t*>(r1);
                afr[mi][2] = *reinterpret_cast<const uint32_t*>(r0 + 8);
                afr[mi][3] = *reinterpret_cast<const uint32_t*>(r1 + 8);
            }
            uint32_t bfr[4][2];
#pragma unroll
            for (int ni = 0; ni < 4; ni++) {
                int n0 = wn + ni * 8 + g;
                const __half* rb = Bs + n0 * HPITCH + ks + 2 * t;
                bfr[ni][0] = *reinterpret_cast<const uint32_t*>(rb);
                bfr[ni][1] = *reinterpret_cast<const uint32_t*>(rb + 8);
            }
#pragma unroll
            for (int mi = 0; mi < 2; mi++)
#pragma unroll
                for (int ni = 0; ni < 4; ni++)
                    mma_f16(acc[mi][ni], afr[mi], bfr[ni]);
        }
    }

    // epilogue: convert to fp16, store half2 per (row, 2 cols)
#pragma unroll
    for (int mi = 0; mi < 2; mi++) {
#pragma unroll
        for (int ni = 0; ni < 4; ni++) {
            int row = mbase + wm + mi * 16 + g;
            int col = colbase + wn + ni * 8 + 2 * t;
            __half2 h0 = __floats2half2_rn(acc[mi][ni][0], acc[mi][ni][1]);
            __half2 h1 = __floats2half2_rn(acc[mi][ni][2], acc[mi][ni][3]);
            *reinterpret_cast<__half2*>(&C[(size_t)row * U_DIM + col])       = h0;
            *reinterpret_cast<__half2*>(&C[(size_t)(row + 8) * U_DIM + col]) = h1;
        }
    }
}

// ---------------------------------------------------------------------------
// 3) Edge aggregation: 64 threads/node, 4 nodes/block; fp16 XV gathers.
// ---------------------------------------------------------------------------
__global__ __launch_bounds__(256)
void agg_k(const __half* __restrict__ XVin,
           const __half* __restrict__ XVout,
           const __half* __restrict__ XVloop,
           const float* __restrict__ gin,
           const float* __restrict__ gout,
           const float* __restrict__ gloop,
           const int* __restrict__ arc_in,
           const int* __restrict__ arc_out,
           const int* __restrict__ lab_in,
           const int* __restrict__ lab_out,
           const float* __restrict__ b_in,
           const float* __restrict__ bg_in,
           const float* __restrict__ b_out,
           const float* __restrict__ bg_out,
           const float* __restrict__ mask_in,
           const float* __restrict__ mask_out,
           const float* __restrict__ mask_loop,
           const float* __restrict__ sent_mask,
           float* __restrict__ Y, __half* __restrict__ Yh, int tb_layout)
{
    int grp = threadIdx.x >> 6;
    int n   = blockIdx.x * 4 + grp;
    int lu  = threadIdx.x & 63;

    __shared__ float p_in[4][DEG], p_out[4][DEG], p_loop[4];
    __shared__ int   s_in[4][DEG], s_out[4][DEG], l_in[4][DEG], l_out[4][DEG];

    if (lu < DEG) {
        int d = lu, e = n * DEG + d;
        int si = arc_in[e] * T_DIM + arc_in[E_EDGES + e];
        int li = lab_in[e];
        float gi = gin[si] + bg_in[li];
        p_in[grp][d] = (1.f / (1.f + __expf(-gi))) * mask_in[n * DEG + d];
        s_in[grp][d] = si; l_in[grp][d] = li;
    } else if (lu < 2 * DEG) {
        int d = lu - DEG, e = n * DEG + d;
        int so = arc_out[e] * T_DIM + arc_out[E_EDGES + e];
        int lo = lab_out[e];
        float go = gout[so] + bg_out[lo];
        p_out[grp][d] = (1.f / (1.f + __expf(-go))) * mask_out[n * DEG + d];
        s_out[grp][d] = so; l_out[grp][d] = lo;
    } else if (lu == 2 * DEG) {
        p_loop[grp] = (1.f / (1.f + __expf(-gloop[n]))) * mask_loop[n];
    }
    __syncthreads();

    const uint2*  XVin2   = reinterpret_cast<const uint2*>(XVin);
    const uint2*  XVout2  = reinterpret_cast<const uint2*>(XVout);
    const uint2*  XVloop2 = reinterpret_cast<const uint2*>(XVloop);
    const float4* bin4    = reinterpret_cast<const float4*>(b_in);
    const float4* bout4   = reinterpret_cast<const float4*>(b_out);

    float pl = p_loop[grp];
    float4 h = h4tof4(XVloop2[(size_t)n * U4 + lu]);
    float4 acc = make_float4(pl * h.x, pl * h.y, pl * h.z, pl * h.w);

#pragma unroll
    for (int d = 0; d < DEG; d++) {
        float p = p_in[grp][d];
        float4 v = h4tof4(XVin2[(size_t)s_in[grp][d] * U4 + lu]);
        float4 bb = bin4[(size_t)l_in[grp][d] * U4 + lu];
        acc.x = fmaf(p, v.x + bb.x, acc.x);
        acc.y = fmaf(p, v.y + bb.y, acc.y);
        acc.z = fmaf(p, v.z + bb.z, acc.z);
        acc.w = fmaf(p, v.w + bb.w, acc.w);
        p = p_out[grp][d];
        v = h4tof4(XVout2[(size_t)s_out[grp][d] * U4 + lu]);
        bb = bout4[(size_t)l_out[grp][d] * U4 + lu];
        acc.x = fmaf(p, v.x + bb.x, acc.x);
        acc.y = fmaf(p, v.y + bb.y, acc.y);
        acc.z = fmaf(p, v.z + bb.z, acc.z);
        acc.w = fmaf(p, v.w + bb.w, acc.w);
    }
    int b = n / T_DIM, t = n % T_DIM;
    float sm = sent_mask[t * B_DIM + b];
    acc.x = fmaxf(acc.x, 0.f) * sm;
    acc.y = fmaxf(acc.y, 0.f) * sm;
    acc.z = fmaxf(acc.z, 0.f) * sm;
    acc.w = fmaxf(acc.w, 0.f) * sm;
    size_t oidx = tb_layout ? ((size_t)t * B_DIM + b) * U4 + lu
                            : (size_t)n * U4 + lu;
    reinterpret_cast<float4*>(Y)[oidx] = acc;
    if (Yh)
        reinterpret_cast<uint2*>(Yh)[(size_t)n * U4 + lu] = f4toh4(acc);
}

// ---------------------------------------------------------------------------
// 4) enc[b] from membank layout
// ---------------------------------------------------------------------------
__global__ void enc_k(const float* __restrict__ MB,
                      const float* __restrict__ sent_mask,
                      float* __restrict__ enc)
{
    int b = blockIdx.x;
    int u = threadIdx.x;  // 0..63
    const float4* M4 = reinterpret_cast<const float4*>(MB);
    float4 s = make_float4(0.f, 0.f, 0.f, 0.f);
#pragma unroll 4
    for (int t = 0; t < T_DIM; t++) {
        float4 v = M4[((size_t)t * B_DIM + b) * U4 + u];
        s.x += v.x; s.y += v.y; s.z += v.z; s.w += v.w;
    }
    __shared__ float ms;
    if (u == 0) {
        float m = 0.f;
        for (int t = 0; t < T_DIM; t++) m += sent_mask[t * B_DIM + b];
        ms = m;
    }
    __syncthreads();
    float inv = 1.f / ms;
    s.x *= inv; s.y *= inv; s.z *= inv; s.w *= inv;
    reinterpret_cast<float4*>(enc)[b * U4 + u] = s;
}

// ---------------------------------------------------------------------------
// 5) h_all[k,b,w] = sum_u enc[b,u] * H[k,u,w]
// ---------------------------------------------------------------------------
__global__ void hall_k(const float* __restrict__ enc,
                       const float* __restrict__ H,
                       float* __restrict__ out)
{
    int k = blockIdx.y, b = blockIdx.x, w = threadIdx.x;
    __shared__ float es[U_DIM];
    es[w] = enc[b * U_DIM + w];
    __syncthreads();
    const float* Hk = H + (size_t)k * U_DIM * U_DIM;
    float acc = 0.f;
#pragma unroll 8
    for (int u = 0; u < U_DIM; u++)
        acc = fmaf(es[u], Hk[u * U_DIM + w], acc);
    out[((size_t)k * B_DIM + b) * U_DIM + w] = acc;
}

// ---------------------------------------------------------------------------
// Launch
// ---------------------------------------------------------------------------
extern "C" void kernel_launch(void* const* d_in, const int* in_sizes, int n_in,
                              void* d_out, int out_size)
{
    const int*   src       = (const int*)  d_in[0];
    const int*   arc_in    = (const int*)  d_in[1];
    const int*   arc_out   = (const int*)  d_in[2];
    const int*   lab_in    = (const int*)  d_in[3];
    const int*   lab_out   = (const int*)  d_in[4];
    const float* mask_in   = (const float*)d_in[5];
    const float* mask_out  = (const float*)d_in[6];
    const float* mask_loop = (const float*)d_in[7];
    const float* sent_mask = (const float*)d_in[8];
    const float* emb       = (const float*)d_in[9];
    const float* V_in      = (const float*)d_in[10];
    const float* b_in      = (const float*)d_in[11];
    const float* Vg_in     = (const float*)d_in[12];
    const float* bg_in     = (const float*)d_in[13];
    const float* V_out     = (const float*)d_in[14];
    const float* b_out     = (const float*)d_in[15];
    const float* Vg_out    = (const float*)d_in[16];
    const float* bg_out    = (const float*)d_in[17];
    const float* W_loop    = (const float*)d_in[18];
    const float* Wg_loop   = (const float*)d_in[19];
    const float* H         = (const float*)d_in[20];
    float* out = (float*)d_out;

    float *pX0, *pX1, *pgin, *pgout, *pgloop, *penc;
    __half *pXh, *pWh, *pXVin, *pXVout, *pXVloop;
    cudaGetSymbolAddress((void**)&pX0,     g_X0);
    cudaGetSymbolAddress((void**)&pX1,     g_X1);
    cudaGetSymbolAddress((void**)&pXh,     g_Xh);
    cudaGetSymbolAddress((void**)&pWh,     g_Wh);
    cudaGetSymbolAddress((void**)&pXVin,   g_XVin);
    cudaGetSymbolAddress((void**)&pXVout,  g_XVout);
    cudaGetSymbolAddress((void**)&pXVloop, g_XVloop);
    cudaGetSymbolAddress((void**)&pgin,    g_gin);
    cudaGetSymbolAddress((void**)&pgout,   g_gout);
    cudaGetSymbolAddress((void**)&pgloop,  g_gloop);
    cudaGetSymbolAddress((void**)&penc,    g_enc);

    cudaFuncSetAttribute(gemm_gate_k,
                         cudaFuncAttributeMaxDynamicSharedMemorySize, SMEM_DYN);

    float* memOut = out + 4 * B_DIM * U_DIM;   // membank region of d_out

    cvtwT_k<<<dim3(8, 8, 6), dim3(32, 32)>>>(V_in, V_out, W_loop, pWh);
    embed_k<<<BT / 4, 256>>>(src, emb, pX0, pXh);

    float* Xcur = pX0;
    for (int l = 0; l < L_LAYERS; l++) {
        const size_t gOff  = (size_t)l * U_DIM;
        const size_t bOff  = (size_t)l * NL_LAB * U_DIM;
        const size_t bgOff = (size_t)l * NL_LAB;
        const int last = (l == L_LAYERS - 1);

        gemm_gate_k<<<TOTAL_BLOCKS, GTHREADS, SMEM_DYN>>>(
            pXh, pWh + (size_t)l * 3 * WSZ,
            pXVin, pXVout, pXVloop,
            Xcur,
            Vg_in + gOff, Vg_out + gOff, Wg_loop + gOff,
            pgin, pgout, pgloop);
        agg_k<<<BT / 4, 256>>>(pXVin, pXVout, pXVloop, pgin, pgout, pgloop,
                               arc_in, arc_out, lab_in, lab_out,
                               b_in + bOff, bg_in + bgOff,
                               b_out + bOff, bg_out + bgOff,
                               mask_in, mask_out, mask_loop, sent_mask,
                               last ? memOut : pX1,
                               last ? nullptr : pXh,
                               last ? 1 : 0);
        Xcur = pX1;
    }

    enc_k<<<B_DIM, 64>>>(memOut, sent_mask, penc);
    hall_k<<<dim3(B_DIM, 4), U_DIM>>>(penc, H, out);
}

// round 13
// speedup vs baseline: 1.3965x; 1.0370x over previous
#include <cuda_runtime.h>
#include <cuda_fp16.h>
#include <cstdint>

// Problem constants
#define L_LAYERS 2
#define U_DIM    256
#define U4       (U_DIM / 4)
#define NL_LAB   64
#define B_DIM    128
#define T_DIM    128
#define DEG      5
#define BT       (B_DIM * T_DIM)          // 16384 nodes
#define E_EDGES  (BT * DEG)               // 81920
#define WSZ      (U_DIM * U_DIM)          // 65536 elems per weight matrix

// ---------------------------------------------------------------------------
// Scratch (device globals — no allocation allowed)
// ---------------------------------------------------------------------------
__device__ float  g_X0[BT * U_DIM];
__device__ float  g_X1[BT * U_DIM];
__device__ __half g_Xh[BT * U_DIM];               // fp16 copy of X (GEMM A)
__device__ __half g_Wh[L_LAYERS * 3 * WSZ];       // fp16 W^T, [l][sel][N][K]
__device__ __half g_XVin[BT * U_DIM];             // fp16 GEMM outputs
__device__ __half g_XVout[BT * U_DIM];
__device__ __half g_XVloop[BT * U_DIM];
__device__ float  g_gin[BT];
__device__ float  g_gout[BT];
__device__ float  g_gloop[BT];
__device__ float  g_enc[B_DIM * U_DIM];

// ---------------------------------------------------------------------------
// helpers
// ---------------------------------------------------------------------------
__device__ __forceinline__ uint2 f4toh4(float4 v) {
    __half2 h01 = __floats2half2_rn(v.x, v.y);
    __half2 h23 = __floats2half2_rn(v.z, v.w);
    uint2 r;
    r.x = *reinterpret_cast<uint32_t*>(&h01);
    r.y = *reinterpret_cast<uint32_t*>(&h23);
    return r;
}

__device__ __forceinline__ float4 h4tof4(uint2 u) {
    __half2 h01 = *reinterpret_cast<__half2*>(&u.x);
    __half2 h23 = *reinterpret_cast<__half2*>(&u.y);
    float2 f01 = __half22float2(h01);
    float2 f23 = __half22float2(h23);
    return make_float4(f01.x, f01.y, f23.x, f23.y);
}

__device__ __forceinline__ void mma_f16(float* d, const uint32_t* a,
                                        const uint32_t* b) {
    asm volatile(
        "mma.sync.aligned.m16n8k16.row.col.f32.f16.f16.f32 "
        "{%0,%1,%2,%3}, {%4,%5,%6,%7}, {%8,%9}, {%0,%1,%2,%3};\n"
        : "+f"(d[0]), "+f"(d[1]), "+f"(d[2]), "+f"(d[3])
        : "r"(a[0]), "r"(a[1]), "r"(a[2]), "r"(a[3]), "r"(b[0]), "r"(b[1]));
}

#define LDSM_X4(r0, r1, r2, r3, addr) \
    asm volatile("ldmatrix.sync.aligned.m8n8.x4.shared.b16 {%0,%1,%2,%3}, [%4];" \
                 : "=r"(r0), "=r"(r1), "=r"(r2), "=r"(r3) : "r"(addr))
#define LDSM_X2(r0, r1, addr) \
    asm volatile("ldmatrix.sync.aligned.m8n8.x2.shared.b16 {%0,%1}, [%2];" \
                 : "=r"(r0), "=r"(r1) : "r"(addr))

__device__ __forceinline__ void cp16(void* dst, const void* src) {
    uint32_t d = (uint32_t)__cvta_generic_to_shared(dst);
    asm volatile("cp.async.cg.shared.global [%0], [%1], 16;\n"
                 :: "r"(d), "l"(src));
}
#define CP_COMMIT() asm volatile("cp.async.commit_group;\n" ::: "memory")
#define CP_WAIT1()  asm volatile("cp.async.wait_group 1;\n" ::: "memory")
#define CP_WAIT0()  asm volatile("cp.async.wait_group 0;\n" ::: "memory")

// ---------------------------------------------------------------------------
// 0) Weight convert + transpose: Wh[l][sel][n][k] = fp16(W[l][sel][k][n])
// ---------------------------------------------------------------------------
__global__ void cvtwT_k(const float* __restrict__ Vin,
                        const float* __restrict__ Vout,
                        const float* __restrict__ Wloop,
                        __half* __restrict__ out)
{
    __shared__ float ts[32][33];
    int z = blockIdx.z;                  // l*3 + sel
    int l = z / 3, sel = z % 3;
    const float* src = ((sel == 0) ? Vin : (sel == 1) ? Vout : Wloop)
                       + (size_t)l * WSZ;
    __half* dst = out + (size_t)z * WSZ;
    int kk = blockIdx.y * 32 + threadIdx.y;
    int nn = blockIdx.x * 32 + threadIdx.x;
    ts[threadIdx.y][threadIdx.x] = src[(size_t)kk * U_DIM + nn];
    __syncthreads();
    int on = blockIdx.x * 32 + threadIdx.y;
    int ok = blockIdx.y * 32 + threadIdx.x;
    dst[(size_t)on * U_DIM + ok] = __float2half_rn(ts[threadIdx.x][threadIdx.y]);
}

// ---------------------------------------------------------------------------
// 1) Embedding gather: X[n=b*T+t] = emb[src[t,b]]; also fp16 copy.
// ---------------------------------------------------------------------------
__global__ void embed_k(const int* __restrict__ src,
                        const float* __restrict__ emb,
                        float* __restrict__ X,
                        __half* __restrict__ Xh)
{
    int grp = threadIdx.x >> 6;
    int n   = blockIdx.x * 4 + grp;
    int lu  = threadIdx.x & 63;
    int b = n / T_DIM, t = n % T_DIM;
    int tok = src[t * B_DIM + b];
    float4 v = reinterpret_cast<const float4*>(emb)[(size_t)tok * U4 + lu];
    reinterpret_cast<float4*>(X)[(size_t)n * U4 + lu] = v;
    reinterpret_cast<uint2*>(Xh)[(size_t)n * U4 + lu] = f4toh4(v);
}

// ---------------------------------------------------------------------------
// 2) Fused FP16 GEMM + gates. 1D grid of 888 blocks, 512 threads.
//      bid in [0,768): GEMM (fp16 in, fp32 accum, fp16 C out), ldmatrix
//                      fragment loads.
//      bid in [768,888): gate GEMVs on fp32 X, grid-stride.
// ---------------------------------------------------------------------------
#define GBM 128
#define GBN 128
#define GBK 32                 // halves per k-tile
#define NT  (U_DIM / GBK)      // 8 k-tiles
#define GTHREADS 512
#define GEMM_BLOCKS 768
#define GATE_BLOCKS 120
#define TOTAL_BLOCKS (GEMM_BLOCKS + GATE_BLOCKS)
#define HPITCH 40              // halves per smem row (80B; ldmatrix conflict-free)
#define A_STAGE_H (GBM * HPITCH)     // 5120 halves
#define B_STAGE_H (GBN * HPITCH)     // 5120 halves
#define SMEM_DYN  (3 * (A_STAGE_H + B_STAGE_H) * 2)   // 61,440 B

__global__ __launch_bounds__(GTHREADS, 2)
void gemm_gate_k(const __half* __restrict__ Ah,
                 const __half* __restrict__ Wh,   // [3][N][K] this layer
                 __half* __restrict__ C0, __half* __restrict__ C1,
                 __half* __restrict__ C2,
                 const float* __restrict__ Aorig,
                 const float* __restrict__ vgin,
                 const float* __restrict__ vgout,
                 const float* __restrict__ wgl,
                 float* __restrict__ gin, float* __restrict__ gout,
                 float* __restrict__ gloop)
{
    const int bid = blockIdx.x;

    // ---------------- gate slice (grid-stride) ----------------
    if (bid >= GEMM_BLOCKS) {
        int gblk = bid - GEMM_BLOCKS;
        int warp = threadIdx.x >> 5;
        int lane = threadIdx.x & 31;
        const float4* v0 = reinterpret_cast<const float4*>(vgin);
        const float4* v1 = reinterpret_cast<const float4*>(vgout);
        const float4* v2 = reinterpret_cast<const float4*>(wgl);
        const int stride = GATE_BLOCKS * 16;
#pragma unroll 1
        for (int n = gblk * 16 + warp; n < BT; n += stride) {
            const float4* xr =
                reinterpret_cast<const float4*>(Aorig + (size_t)n * U_DIM);
            float s0 = 0.f, s1 = 0.f, s2 = 0.f;
#pragma unroll
            for (int k = lane; k < U4; k += 32) {
                float4 x = xr[k];
                float4 a = v0[k], b = v1[k], c = v2[k];
                s0 += x.x * a.x + x.y * a.y + x.z * a.z + x.w * a.w;
                s1 += x.x * b.x + x.y * b.y + x.z * b.z + x.w * b.w;
                s2 += x.x * c.x + x.y * c.y + x.z * c.z + x.w * c.w;
            }
#pragma unroll
            for (int off = 16; off > 0; off >>= 1) {
                s0 += __shfl_down_sync(0xffffffffu, s0, off);
                s1 += __shfl_down_sync(0xffffffffu, s1, off);
                s2 += __shfl_down_sync(0xffffffffu, s2, off);
            }
            if (lane == 0) { gin[n] = s0; gout[n] = s1; gloop[n] = s2; }
        }
        return;
    }

    // ---------------- GEMM slice ----------------
    const int xb      = bid & 127;
    const int yb      = bid >> 7;              // 0..5
    const int sel     = yb >> 1;
    const int colbase = (yb & 1) * GBN;
    const __half* __restrict__ W = Wh + (size_t)sel * WSZ;   // [N][K]
    __half* __restrict__ C       = (sel == 0) ? C0 : ((sel == 1) ? C1 : C2);
    const int mbase = xb * GBM;

    extern __shared__ __align__(16) __half hsm[];
    __half* Asm = hsm;                         // 3 stages of [GBM][HPITCH]
    __half* Bsm = hsm + 3 * A_STAGE_H;         // 3 stages of [GBN][HPITCH]

    const int tid  = threadIdx.x;
    const int lane = tid & 31;
    const int warp = tid >> 5;
    const int wm   = (warp & 3) * 32;          // warp M offset
    const int wn   = (warp >> 2) * 32;         // warp N offset
    const int g    = lane >> 2;                // 0..7
    const int t    = lane & 3;                 // 0..3

    // cp.async: one 16B (8 halves) per thread per operand per tile
    const int ldRow = tid >> 2;                // 0..127
    const int ldH   = (tid & 3) * 8;           // 0,8,16,24 halves

    const __half* Abase = Ah + (size_t)(mbase + ldRow) * U_DIM + ldH;
    const __half* Wbase = W + (size_t)(colbase + ldRow) * U_DIM + ldH;
    __half* AsmRow = Asm + ldRow * HPITCH + ldH;
    __half* BsmRow = Bsm + ldRow * HPITCH + ldH;

    // ldmatrix lane-address offsets (bytes)
    const uint32_t asmB = (uint32_t)__cvta_generic_to_shared(Asm);
    const uint32_t bsmB = (uint32_t)__cvta_generic_to_shared(Bsm);
    // A x4: lane l -> row wm+mi*16+(l&15), k-offset (l>>4)*8
    const uint32_t aOff0 =
        ((wm + (lane & 15)) * HPITCH + ((lane >> 4) << 3)) * 2;
    const uint32_t aOff1 = aOff0 + 16 * HPITCH * 2;
    // B x2: lane l (l<16 used) -> row wn+ni*8+(l&7), k-offset ((l>>3)&1)*8
    uint32_t bOff[4];
#pragma unroll
    for (int ni = 0; ni < 4; ni++)
        bOff[ni] = ((wn + ni * 8 + (lane & 7)) * HPITCH +
                    (((lane >> 3) & 1) << 3)) * 2;

    float acc[2][4][4];
#pragma unroll
    for (int mi = 0; mi < 2; mi++)
#pragma unroll
        for (int ni = 0; ni < 4; ni++)
#pragma unroll
            for (int c = 0; c < 4; c++) acc[mi][ni][c] = 0.f;

    // prologue: tiles 0 and 1 into stages 0 and 1
    cp16(AsmRow,             Abase);
    cp16(BsmRow,             Wbase);
    CP_COMMIT();
    cp16(AsmRow + A_STAGE_H, Abase + GBK);
    cp16(BsmRow + B_STAGE_H, Wbase + GBK);
    CP_COMMIT();

#pragma unroll 1
    for (int tile = 0; tile < NT; tile++) {
        if (tile < NT - 1) { CP_WAIT1(); } else { CP_WAIT0(); }
        __syncthreads();   // tile data visible; stage (tile+2)%3 free

        int nxt = tile + 2;
        if (nxt < NT) {
            int s  = nxt % 3;
            int k0 = nxt * GBK;
            cp16(AsmRow + s * A_STAGE_H, Abase + k0);
            cp16(BsmRow + s * B_STAGE_H, Wbase + k0);
            CP_COMMIT();
        }

        const int st = tile % 3;
        const uint32_t stA = asmB + st * (A_STAGE_H * 2);
        const uint32_t stB = bsmB + st * (B_STAGE_H * 2);
#pragma unroll
        for (int ks = 0; ks < GBK; ks += 16) {
            const uint32_t kByte = ks * 2;
            uint32_t afr[2][4];
            LDSM_X4(afr[0][0], afr[0][1], afr[0][2], afr[0][3],
                    stA + aOff0 + kByte);
            LDSM_X4(afr[1][0], afr[1][1], afr[1][2], afr[1][3],
                    stA + aOff1 + kByte);
            uint32_t bfr[4][2];
#pragma unroll
            for (int ni = 0; ni < 4; ni++)
                LDSM_X2(bfr[ni][0], bfr[ni][1], stB + bOff[ni] + kByte);
#pragma unroll
            for (int mi = 0; mi < 2; mi++)
#pragma unroll
                for (int ni = 0; ni < 4; ni++)
                    mma_f16(acc[mi][ni], afr[mi], bfr[ni]);
        }
    }

    // epilogue: convert to fp16, store half2 per (row, 2 cols)
#pragma unroll
    for (int mi = 0; mi < 2; mi++) {
#pragma unroll
        for (int ni = 0; ni < 4; ni++) {
            int row = mbase + wm + mi * 16 + g;
            int col = colbase + wn + ni * 8 + 2 * t;
            __half2 h0 = __floats2half2_rn(acc[mi][ni][0], acc[mi][ni][1]);
            __half2 h1 = __floats2half2_rn(acc[mi][ni][2], acc[mi][ni][3]);
            *reinterpret_cast<__half2*>(&C[(size_t)row * U_DIM + col])       = h0;
            *reinterpret_cast<__half2*>(&C[(size_t)(row + 8) * U_DIM + col]) = h1;
        }
    }
}

// ---------------------------------------------------------------------------
// 3) Edge aggregation: 64 threads/node, 4 nodes/block; fp16 XV gathers.
// ---------------------------------------------------------------------------
__global__ __launch_bounds__(256)
void agg_k(const __half* __restrict__ XVin,
           const __half* __restrict__ XVout,
           const __half* __restrict__ XVloop,
           const float* __restrict__ gin,
           const float* __restrict__ gout,
           const float* __restrict__ gloop,
           const int* __restrict__ arc_in,
           const int* __restrict__ arc_out,
           const int* __restrict__ lab_in,
           const int* __restrict__ lab_out,
           const float* __restrict__ b_in,
           const float* __restrict__ bg_in,
           const float* __restrict__ b_out,
           const float* __restrict__ bg_out,
           const float* __restrict__ mask_in,
           const float* __restrict__ mask_out,
           const float* __restrict__ mask_loop,
           const float* __restrict__ sent_mask,
           float* __restrict__ Y, __half* __restrict__ Yh, int tb_layout)
{
    int grp = threadIdx.x >> 6;
    int n   = blockIdx.x * 4 + grp;
    int lu  = threadIdx.x & 63;

    __shared__ float p_in[4][DEG], p_out[4][DEG], p_loop[4];
    __shared__ int   s_in[4][DEG], s_out[4][DEG], l_in[4][DEG], l_out[4][DEG];

    if (lu < DEG) {
        int d = lu, e = n * DEG + d;
        int si = arc_in[e] * T_DIM + arc_in[E_EDGES + e];
        int li = lab_in[e];
        float gi = gin[si] + bg_in[li];
        p_in[grp][d] = (1.f / (1.f + __expf(-gi))) * mask_in[n * DEG + d];
        s_in[grp][d] = si; l_in[grp][d] = li;
    } else if (lu < 2 * DEG) {
        int d = lu - DEG, e = n * DEG + d;
        int so = arc_out[e] * T_DIM + arc_out[E_EDGES + e];
        int lo = lab_out[e];
        float go = gout[so] + bg_out[lo];
        p_out[grp][d] = (1.f / (1.f + __expf(-go))) * mask_out[n * DEG + d];
        s_out[grp][d] = so; l_out[grp][d] = lo;
    } else if (lu == 2 * DEG) {
        p_loop[grp] = (1.f / (1.f + __expf(-gloop[n]))) * mask_loop[n];
    }
    __syncthreads();

    const uint2*  XVin2   = reinterpret_cast<const uint2*>(XVin);
    const uint2*  XVout2  = reinterpret_cast<const uint2*>(XVout);
    const uint2*  XVloop2 = reinterpret_cast<const uint2*>(XVloop);
    const float4* bin4    = reinterpret_cast<const float4*>(b_in);
    const float4* bout4   = reinterpret_cast<const float4*>(b_out);

    float pl = p_loop[grp];
    float4 h = h4tof4(XVloop2[(size_t)n * U4 + lu]);
    float4 acc = make_float4(pl * h.x, pl * h.y, pl * h.z, pl * h.w);

#pragma unroll
    for (int d = 0; d < DEG; d++) {
        float p = p_in[grp][d];
        float4 v = h4tof4(XVin2[(size_t)s_in[grp][d] * U4 + lu]);
        float4 bb = bin4[(size_t)l_in[grp][d] * U4 + lu];
        acc.x = fmaf(p, v.x + bb.x, acc.x);
        acc.y = fmaf(p, v.y + bb.y, acc.y);
        acc.z = fmaf(p, v.z + bb.z, acc.z);
        acc.w = fmaf(p, v.w + bb.w, acc.w);
        p = p_out[grp][d];
        v = h4tof4(XVout2[(size_t)s_out[grp][d] * U4 + lu]);
        bb = bout4[(size_t)l_out[grp][d] * U4 + lu];
        acc.x = fmaf(p, v.x + bb.x, acc.x);
        acc.y = fmaf(p, v.y + bb.y, acc.y);
        acc.z = fmaf(p, v.z + bb.z, acc.z);
        acc.w = fmaf(p, v.w + bb.w, acc.w);
    }
    int b = n / T_DIM, t = n % T_DIM;
    float sm = sent_mask[t * B_DIM + b];
    acc.x = fmaxf(acc.x, 0.f) * sm;
    acc.y = fmaxf(acc.y, 0.f) * sm;
    acc.z = fmaxf(acc.z, 0.f) * sm;
    acc.w = fmaxf(acc.w, 0.f) * sm;
    size_t oidx = tb_layout ? ((size_t)t * B_DIM + b) * U4 + lu
                            : (size_t)n * U4 + lu;
    reinterpret_cast<float4*>(Y)[oidx] = acc;
    if (Yh)
        reinterpret_cast<uint2*>(Yh)[(size_t)n * U4 + lu] = f4toh4(acc);
}

// ---------------------------------------------------------------------------
// 4) enc[b] from membank layout
// ---------------------------------------------------------------------------
__global__ void enc_k(const float* __restrict__ MB,
                      const float* __restrict__ sent_mask,
                      float* __restrict__ enc)
{
    int b = blockIdx.x;
    int u = threadIdx.x;  // 0..63
    const float4* M4 = reinterpret_cast<const float4*>(MB);
    float4 s = make_float4(0.f, 0.f, 0.f, 0.f);
#pragma unroll 4
    for (int t = 0; t < T_DIM; t++) {
        float4 v = M4[((size_t)t * B_DIM + b) * U4 + u];
        s.x += v.x; s.y += v.y; s.z += v.z; s.w += v.w;
    }
    __shared__ float ms;
    if (u == 0) {
        float m = 0.f;
        for (int t = 0; t < T_DIM; t++) m += sent_mask[t * B_DIM + b];
        ms = m;
    }
    __syncthreads();
    float inv = 1.f / ms;
    s.x *= inv; s.y *= inv; s.z *= inv; s.w *= inv;
    reinterpret_cast<float4*>(enc)[b * U4 + u] = s;
}

// ---------------------------------------------------------------------------
// 5) h_all[k,b,w] = sum_u enc[b,u] * H[k,u,w]
// ---------------------------------------------------------------------------
__global__ void hall_k(const float* __restrict__ enc,
                       const float* __restrict__ H,
                       float* __restrict__ out)
{
    int k = blockIdx.y, b = blockIdx.x, w = threadIdx.x;
    __shared__ float es[U_DIM];
    es[w] = enc[b * U_DIM + w];
    __syncthreads();
    const float* Hk = H + (size_t)k * U_DIM * U_DIM;
    float acc = 0.f;
#pragma unroll 8
    for (int u = 0; u < U_DIM; u++)
        acc = fmaf(es[u], Hk[u * U_DIM + w], acc);
    out[((size_t)k * B_DIM + b) * U_DIM + w] = acc;
}

// ---------------------------------------------------------------------------
// Launch
// ---------------------------------------------------------------------------
extern "C" void kernel_launch(void* const* d_in, const int* in_sizes, int n_in,
                              void* d_out, int out_size)
{
    const int*   src       = (const int*)  d_in[0];
    const int*   arc_in    = (const int*)  d_in[1];
    const int*   arc_out   = (const int*)  d_in[2];
    const int*   lab_in    = (const int*)  d_in[3];
    const int*   lab_out   = (const int*)  d_in[4];
    const float* mask_in   = (const float*)d_in[5];
    const float* mask_out  = (const float*)d_in[6];
    const float* mask_loop = (const float*)d_in[7];
    const float* sent_mask = (const float*)d_in[8];
    const float* emb       = (const float*)d_in[9];
    const float* V_in      = (const float*)d_in[10];
    const float* b_in      = (const float*)d_in[11];
    const float* Vg_in     = (const float*)d_in[12];
    const float* bg_in     = (const float*)d_in[13];
    const float* V_out     = (const float*)d_in[14];
    const float* b_out     = (const float*)d_in[15];
    const float* Vg_out    = (const float*)d_in[16];
    const float* bg_out    = (const float*)d_in[17];
    const float* W_loop    = (const float*)d_in[18];
    const float* Wg_loop   = (const float*)d_in[19];
    const float* H         = (const float*)d_in[20];
    float* out = (float*)d_out;

    float *pX0, *pX1, *pgin, *pgout, *pgloop, *penc;
    __half *pXh, *pWh, *pXVin, *pXVout, *pXVloop;
    cudaGetSymbolAddress((void**)&pX0,     g_X0);
    cudaGetSymbolAddress((void**)&pX1,     g_X1);
    cudaGetSymbolAddress((void**)&pXh,     g_Xh);
    cudaGetSymbolAddress((void**)&pWh,     g_Wh);
    cudaGetSymbolAddress((void**)&pXVin,   g_XVin);
    cudaGetSymbolAddress((void**)&pXVout,  g_XVout);
    cudaGetSymbolAddress((void**)&pXVloop, g_XVloop);
    cudaGetSymbolAddress((void**)&pgin,    g_gin);
    cudaGetSymbolAddress((void**)&pgout,   g_gout);
    cudaGetSymbolAddress((void**)&pgloop,  g_gloop);
    cudaGetSymbolAddress((void**)&penc,    g_enc);

    cudaFuncSetAttribute(gemm_gate_k,
                         cudaFuncAttributeMaxDynamicSharedMemorySize, SMEM_DYN);

    float* memOut = out + 4 * B_DIM * U_DIM;   // membank region of d_out

    cvtwT_k<<<dim3(8, 8, 6), dim3(32, 32)>>>(V_in, V_out, W_loop, pWh);
    embed_k<<<BT / 4, 256>>>(src, emb, pX0, pXh);

    float* Xcur = pX0;
    for (int l = 0; l < L_LAYERS; l++) {
        const size_t gOff  = (size_t)l * U_DIM;
        const size_t bOff  = (size_t)l * NL_LAB * U_DIM;
        const size_t bgOff = (size_t)l * NL_LAB;
        const int last = (l == L_LAYERS - 1);

        gemm_gate_k<<<TOTAL_BLOCKS, GTHREADS, SMEM_DYN>>>(
            pXh, pWh + (size_t)l * 3 * WSZ,
            pXVin, pXVout, pXVloop,
            Xcur,
            Vg_in + gOff, Vg_out + gOff, Wg_loop + gOff,
            pgin, pgout, pgloop);
        agg_k<<<BT / 4, 256>>>(pXVin, pXVout, pXVloop, pgin, pgout, pgloop,
                               arc_in, arc_out, lab_in, lab_out,
                               b_in + bOff, bg_in + bgOff,
                               b_out + bOff, bg_out + bgOff,
                               mask_in, mask_out, mask_loop, sent_mask,
                               last ? memOut : pX1,
                               last ? nullptr : pXh,
                               last ? 1 : 0);
        Xcur = pX1;
    }

    enc_k<<<B_DIM, 64>>>(memOut, sent_mask, penc);
    hall_k<<<dim3(B_DIM, 4), U_DIM>>>(penc, H, out);
}

// round 14
// speedup vs baseline: 1.5286x; 1.0946x over previous
#include <cuda_runtime.h>
#include <cuda_fp16.h>
#include <cstdint>

// Problem constants
#define L_LAYERS 2
#define U_DIM    256
#define U4       (U_DIM / 4)
#define U8       (U_DIM / 8)
#define NL_LAB   64
#define B_DIM    128
#define T_DIM    128
#define DEG      5
#define BT       (B_DIM * T_DIM)          // 16384 nodes
#define E_EDGES  (BT * DEG)               // 81920
#define WSZ      (U_DIM * U_DIM)          // 65536 elems per weight matrix

// ---------------------------------------------------------------------------
// Scratch (device globals — no allocation allowed)
// ---------------------------------------------------------------------------
__device__ __half g_Xh[BT * U_DIM];               // fp16 X (GEMM A + gates)
__device__ __half g_Wh[L_LAYERS * 3 * WSZ];       // fp16 W^T, [l][sel][N][K]
__device__ __half g_binh[L_LAYERS * NL_LAB * U_DIM];   // fp16 label biases
__device__ __half g_bouth[L_LAYERS * NL_LAB * U_DIM];
__device__ __half g_XVin[BT * U_DIM];             // fp16 GEMM outputs
__device__ __half g_XVout[BT * U_DIM];
__device__ __half g_XVloop[BT * U_DIM];
__device__ float  g_gin[BT];
__device__ float  g_gout[BT];
__device__ float  g_gloop[BT];
__device__ float  g_enc[B_DIM * U_DIM];

// ---------------------------------------------------------------------------
// helpers
// ---------------------------------------------------------------------------
__device__ __forceinline__ uint2 f4toh4(float4 v) {
    __half2 h01 = __floats2half2_rn(v.x, v.y);
    __half2 h23 = __floats2half2_rn(v.z, v.w);
    uint2 r;
    r.x = *reinterpret_cast<uint32_t*>(&h01);
    r.y = *reinterpret_cast<uint32_t*>(&h23);
    return r;
}

__device__ __forceinline__ void h8tof8(uint4 u, float* f) {
    float2 p;
    p = __half22float2(*reinterpret_cast<__half2*>(&u.x)); f[0] = p.x; f[1] = p.y;
    p = __half22float2(*reinterpret_cast<__half2*>(&u.y)); f[2] = p.x; f[3] = p.y;
    p = __half22float2(*reinterpret_cast<__half2*>(&u.z)); f[4] = p.x; f[5] = p.y;
    p = __half22float2(*reinterpret_cast<__half2*>(&u.w)); f[6] = p.x; f[7] = p.y;
}

__device__ __forceinline__ void mma_f16(float* d, const uint32_t* a,
                                        const uint32_t* b) {
    asm volatile(
        "mma.sync.aligned.m16n8k16.row.col.f32.f16.f16.f32 "
        "{%0,%1,%2,%3}, {%4,%5,%6,%7}, {%8,%9}, {%0,%1,%2,%3};\n"
        : "+f"(d[0]), "+f"(d[1]), "+f"(d[2]), "+f"(d[3])
        : "r"(a[0]), "r"(a[1]), "r"(a[2]), "r"(a[3]), "r"(b[0]), "r"(b[1]));
}

#define LDSM_X4(r0, r1, r2, r3, addr) \
    asm volatile("ldmatrix.sync.aligned.m8n8.x4.shared.b16 {%0,%1,%2,%3}, [%4];" \
                 : "=r"(r0), "=r"(r1), "=r"(r2), "=r"(r3) : "r"(addr))
#define LDSM_X2(r0, r1, addr) \
    asm volatile("ldmatrix.sync.aligned.m8n8.x2.shared.b16 {%0,%1}, [%2];" \
                 : "=r"(r0), "=r"(r1) : "r"(addr))

__device__ __forceinline__ void cp16(void* dst, const void* src) {
    uint32_t d = (uint32_t)__cvta_generic_to_shared(dst);
    asm volatile("cp.async.cg.shared.global [%0], [%1], 16;\n"
                 :: "r"(d), "l"(src));
}
#define CP_COMMIT() asm volatile("cp.async.commit_group;\n" ::: "memory")
#define CP_WAIT1()  asm volatile("cp.async.wait_group 1;\n" ::: "memory")
#define CP_WAIT0()  asm volatile("cp.async.wait_group 0;\n" ::: "memory")

// ---------------------------------------------------------------------------
// 0a) Weight convert + transpose: Wh[l][sel][n][k] = fp16(W[l][sel][k][n])
// ---------------------------------------------------------------------------
__global__ void cvtwT_k(const float* __restrict__ Vin,
                        const float* __restrict__ Vout,
                        const float* __restrict__ Wloop,
                        __half* __restrict__ out)
{
    __shared__ float ts[32][33];
    int z = blockIdx.z;                  // l*3 + sel
    int l = z / 3, sel = z % 3;
    const float* src = ((sel == 0) ? Vin : (sel == 1) ? Vout : Wloop)
                       + (size_t)l * WSZ;
    __half* dst = out + (size_t)z * WSZ;
    int kk = blockIdx.y * 32 + threadIdx.y;
    int nn = blockIdx.x * 32 + threadIdx.x;
    ts[threadIdx.y][threadIdx.x] = src[(size_t)kk * U_DIM + nn];
    __syncthreads();
    int on = blockIdx.x * 32 + threadIdx.y;
    int ok = blockIdx.y * 32 + threadIdx.x;
    dst[(size_t)on * U_DIM + ok] = __float2half_rn(ts[threadIdx.x][threadIdx.y]);
}

// ---------------------------------------------------------------------------
// 0b) Bias convert: fp32 [L*NL*U] -> fp16, both in and out tables.
// ---------------------------------------------------------------------------
__global__ void cvtb_k(const float* __restrict__ b_in,
                       const float* __restrict__ b_out,
                       __half* __restrict__ binh,
                       __half* __restrict__ bouth)
{
    int idx = blockIdx.x * 256 + threadIdx.x;    // float4 index
    float4 v = reinterpret_cast<const float4*>(b_in)[idx];
    reinterpret_cast<uint2*>(binh)[idx] = f4toh4(v);
    v = reinterpret_cast<const float4*>(b_out)[idx];
    reinterpret_cast<uint2*>(bouth)[idx] = f4toh4(v);
}

// ---------------------------------------------------------------------------
// 1) Embedding gather: Xh[n=b*T+t] = fp16(emb[src[t,b]])
// ---------------------------------------------------------------------------
__global__ void embed_k(const int* __restrict__ src,
                        const float* __restrict__ emb,
                        __half* __restrict__ Xh)
{
    int grp = threadIdx.x >> 6;
    int n   = blockIdx.x * 4 + grp;
    int lu  = threadIdx.x & 63;
    int b = n / T_DIM, t = n % T_DIM;
    int tok = src[t * B_DIM + b];
    float4 v = reinterpret_cast<const float4*>(emb)[(size_t)tok * U4 + lu];
    reinterpret_cast<uint2*>(Xh)[(size_t)n * U4 + lu] = f4toh4(v);
}

// ---------------------------------------------------------------------------
// 2) Fused FP16 GEMM + gates. 1D grid of 888 blocks, 512 threads.
//      bid in [0,768): GEMM (fp16 in, fp32 accum, fp16 C out), ldmatrix.
//      bid in [768,888): gate GEMVs on fp16 X, grid-stride.
// ---------------------------------------------------------------------------
#define GBM 128
#define GBN 128
#define GBK 32                 // halves per k-tile
#define NT  (U_DIM / GBK)      // 8 k-tiles
#define GTHREADS 512
#define GEMM_BLOCKS 768
#define GATE_BLOCKS 120
#define TOTAL_BLOCKS (GEMM_BLOCKS + GATE_BLOCKS)
#define HPITCH 40              // halves per smem row (80B; ldmatrix conflict-free)
#define A_STAGE_H (GBM * HPITCH)     // 5120 halves
#define B_STAGE_H (GBN * HPITCH)     // 5120 halves
#define SMEM_DYN  (3 * (A_STAGE_H + B_STAGE_H) * 2)   // 61,440 B

__global__ __launch_bounds__(GTHREADS, 2)
void gemm_gate_k(const __half* __restrict__ Ah,
                 const __half* __restrict__ Wh,   // [3][N][K] this layer
                 __half* __restrict__ C0, __half* __restrict__ C1,
                 __half* __restrict__ C2,
                 const float* __restrict__ vgin,
                 const float* __restrict__ vgout,
                 const float* __restrict__ wgl,
                 float* __restrict__ gin, float* __restrict__ gout,
                 float* __restrict__ gloop)
{
    const int bid = blockIdx.x;

    // ---------------- gate slice (grid-stride, fp16 X) ----------------
    if (bid >= GEMM_BLOCKS) {
        int gblk = bid - GEMM_BLOCKS;
        int warp = threadIdx.x >> 5;
        int lane = threadIdx.x & 31;
        const float4* v0 = reinterpret_cast<const float4*>(vgin);
        const float4* v1 = reinterpret_cast<const float4*>(vgout);
        const float4* v2 = reinterpret_cast<const float4*>(wgl);
        const int stride = GATE_BLOCKS * 16;
#pragma unroll 1
        for (int n = gblk * 16 + warp; n < BT; n += stride) {
            // one uint4 (8 halves) per lane covers U=256
            uint4 xu = reinterpret_cast<const uint4*>(
                Ah + (size_t)n * U_DIM)[lane];
            float x[8];
            h8tof8(xu, x);
            float s0 = 0.f, s1 = 0.f, s2 = 0.f;
            int base = lane * 2;    // float4 index into gate vectors
#pragma unroll
            for (int q = 0; q < 2; q++) {
                float4 a = v0[base + q], b = v1[base + q], c = v2[base + q];
                float* xx = x + q * 4;
                s0 += xx[0] * a.x + xx[1] * a.y + xx[2] * a.z + xx[3] * a.w;
                s1 += xx[0] * b.x + xx[1] * b.y + xx[2] * b.z + xx[3] * b.w;
                s2 += xx[0] * c.x + xx[1] * c.y + xx[2] * c.z + xx[3] * c.w;
            }
#pragma unroll
            for (int off = 16; off > 0; off >>= 1) {
                s0 += __shfl_down_sync(0xffffffffu, s0, off);
                s1 += __shfl_down_sync(0xffffffffu, s1, off);
                s2 += __shfl_down_sync(0xffffffffu, s2, off);
            }
            if (lane == 0) { gin[n] = s0; gout[n] = s1; gloop[n] = s2; }
        }
        return;
    }

    // ---------------- GEMM slice ----------------
    const int xb      = bid & 127;
    const int yb      = bid >> 7;              // 0..5
    const int sel     = yb >> 1;
    const int colbase = (yb & 1) * GBN;
    const __half* __restrict__ W = Wh + (size_t)sel * WSZ;   // [N][K]
    __half* __restrict__ C       = (sel == 0) ? C0 : ((sel == 1) ? C1 : C2);
    const int mbase = xb * GBM;

    extern __shared__ __align__(16) __half hsm[];
    __half* Asm = hsm;                         // 3 stages of [GBM][HPITCH]
    __half* Bsm = hsm + 3 * A_STAGE_H;         // 3 stages of [GBN][HPITCH]

    const int tid  = threadIdx.x;
    const int lane = tid & 31;
    const int warp = tid >> 5;
    const int wm   = (warp & 3) * 32;          // warp M offset
    const int wn   = (warp >> 2) * 32;         // warp N offset
    const int g    = lane >> 2;                // 0..7
    const int t    = lane & 3;                 // 0..3

    const int ldRow = tid >> 2;                // 0..127
    const int ldH   = (tid & 3) * 8;           // 0,8,16,24 halves

    const __half* Abase = Ah + (size_t)(mbase + ldRow) * U_DIM + ldH;
    const __half* Wbase = W + (size_t)(colbase + ldRow) * U_DIM + ldH;
    __half* AsmRow = Asm + ldRow * HPITCH + ldH;
    __half* BsmRow = Bsm + ldRow * HPITCH + ldH;

    const uint32_t asmB = (uint32_t)__cvta_generic_to_shared(Asm);
    const uint32_t bsmB = (uint32_t)__cvta_generic_to_shared(Bsm);
    const uint32_t aOff0 =
        ((wm + (lane & 15)) * HPITCH + ((lane >> 4) << 3)) * 2;
    const uint32_t aOff1 = aOff0 + 16 * HPITCH * 2;
    uint32_t bOff[4];
#pragma unroll
    for (int ni = 0; ni < 4; ni++)
        bOff[ni] = ((wn + ni * 8 + (lane & 7)) * HPITCH +
                    (((lane >> 3) & 1) << 3)) * 2;

    float acc[2][4][4];
#pragma unroll
    for (int mi = 0; mi < 2; mi++)
#pragma unroll
        for (int ni = 0; ni < 4; ni++)
#pragma unroll
            for (int c = 0; c < 4; c++) acc[mi][ni][c] = 0.f;

    cp16(AsmRow,             Abase);
    cp16(BsmRow,             Wbase);
    CP_COMMIT();
    cp16(AsmRow + A_STAGE_H, Abase + GBK);
    cp16(BsmRow + B_STAGE_H, Wbase + GBK);
    CP_COMMIT();

#pragma unroll 1
    for (int tile = 0; tile < NT; tile++) {
        if (tile < NT - 1) { CP_WAIT1(); } else { CP_WAIT0(); }
        __syncthreads();

        int nxt = tile + 2;
        if (nxt < NT) {
            int s  = nxt % 3;
            int k0 = nxt * GBK;
            cp16(AsmRow + s * A_STAGE_H, Abase + k0);
            cp16(BsmRow + s * B_STAGE_H, Wbase + k0);
            CP_COMMIT();
        }

        const int st = tile % 3;
        const uint32_t stA = asmB + st * (A_STAGE_H * 2);
        const uint32_t stB = bsmB + st * (B_STAGE_H * 2);
#pragma unroll
        for (int ks = 0; ks < GBK; ks += 16) {
            const uint32_t kByte = ks * 2;
            uint32_t afr[2][4];
            LDSM_X4(afr[0][0], afr[0][1], afr[0][2], afr[0][3],
                    stA + aOff0 + kByte);
            LDSM_X4(afr[1][0], afr[1][1], afr[1][2], afr[1][3],
                    stA + aOff1 + kByte);
            uint32_t bfr[4][2];
#pragma unroll
            for (int ni = 0; ni < 4; ni++)
                LDSM_X2(bfr[ni][0], bfr[ni][1], stB + bOff[ni] + kByte);
#pragma unroll
            for (int mi = 0; mi < 2; mi++)
#pragma unroll
                for (int ni = 0; ni < 4; ni++)
                    mma_f16(acc[mi][ni], afr[mi], bfr[ni]);
        }
    }

    // epilogue: fp16 stores
#pragma unroll
    for (int mi = 0; mi < 2; mi++) {
#pragma unroll
        for (int ni = 0; ni < 4; ni++) {
            int row = mbase + wm + mi * 16 + g;
            int col = colbase + wn + ni * 8 + 2 * t;
            __half2 h0 = __floats2half2_rn(acc[mi][ni][0], acc[mi][ni][1]);
            __half2 h1 = __floats2half2_rn(acc[mi][ni][2], acc[mi][ni][3]);
            *reinterpret_cast<__half2*>(&C[(size_t)row * U_DIM + col])       = h0;
            *reinterpret_cast<__half2*>(&C[(size_t)(row + 8) * U_DIM + col]) = h1;
        }
    }
}

// ---------------------------------------------------------------------------
// 3) Edge aggregation: 32 threads/node, 8 nodes/block; uint4 fp16 gathers,
//    fp16 biases, fp32 accumulation.
//    Y  != nullptr -> fp32 [t,b,u] output (last layer / d_out membank)
//    Yh != nullptr -> fp16 node-major output (next layer's X)
// ---------------------------------------------------------------------------
__global__ __launch_bounds__(256)
void agg_k(const __half* __restrict__ XVin,
           const __half* __restrict__ XVout,
           const __half* __restrict__ XVloop,
           const float* __restrict__ gin,
           const float* __restrict__ gout,
           const float* __restrict__ gloop,
           const int* __restrict__ arc_in,
           const int* __restrict__ arc_out,
           const int* __restrict__ lab_in,
           const int* __restrict__ lab_out,
           const __half* __restrict__ binh,    // [NL,U] fp16 this layer
           const float* __restrict__ bg_in,
           const __half* __restrict__ bouth,
           const float* __restrict__ bg_out,
           const float* __restrict__ mask_in,
           const float* __restrict__ mask_out,
           const float* __restrict__ mask_loop,
           const float* __restrict__ sent_mask,
           float* __restrict__ Y, __half* __restrict__ Yh)
{
    int grp = threadIdx.x >> 5;      // node within block (0..7)
    int n   = blockIdx.x * 8 + grp;
    int lu  = threadIdx.x & 31;      // uint4 lane over U (32 x 8 halves)

    __shared__ float p_in[8][DEG], p_out[8][DEG], p_loop[8];
    __shared__ int   s_in[8][DEG], s_out[8][DEG], l_in[8][DEG], l_out[8][DEG];

    if (lu < DEG) {
        int d = lu, e = n * DEG + d;
        int si = arc_in[e] * T_DIM + arc_in[E_EDGES + e];
        int li = lab_in[e];
        float gi = gin[si] + bg_in[li];
        p_in[grp][d] = (1.f / (1.f + __expf(-gi))) * mask_in[n * DEG + d];
        s_in[grp][d] = si; l_in[grp][d] = li;
    } else if (lu < 2 * DEG) {
        int d = lu - DEG, e = n * DEG + d;
        int so = arc_out[e] * T_DIM + arc_out[E_EDGES + e];
        int lo = lab_out[e];
        float go = gout[so] + bg_out[lo];
        p_out[grp][d] = (1.f / (1.f + __expf(-go))) * mask_out[n * DEG + d];
        s_out[grp][d] = so; l_out[grp][d] = lo;
    } else if (lu == 2 * DEG) {
        p_loop[grp] = (1.f / (1.f + __expf(-gloop[n]))) * mask_loop[n];
    }
    __syncthreads();

    const uint4* XVin4   = reinterpret_cast<const uint4*>(XVin);
    const uint4* XVout4  = reinterpret_cast<const uint4*>(XVout);
    const uint4* XVloop4 = reinterpret_cast<const uint4*>(XVloop);
    const uint4* bin4    = reinterpret_cast<const uint4*>(binh);
    const uint4* bout4   = reinterpret_cast<const uint4*>(bouth);

    float acc[8], v[8], bb[8];
    {
        float pl = p_loop[grp];
        h8tof8(XVloop4[(size_t)n * U8 + lu], v);
#pragma unroll
        for (int q = 0; q < 8; q++) acc[q] = pl * v[q];
    }

#pragma unroll
    for (int d = 0; d < DEG; d++) {
        float p = p_in[grp][d];
        h8tof8(XVin4[(size_t)s_in[grp][d] * U8 + lu], v);
        h8tof8(bin4[(size_t)l_in[grp][d] * U8 + lu], bb);
#pragma unroll
        for (int q = 0; q < 8; q++)
            acc[q] = fmaf(p, v[q] + bb[q], acc[q]);
        p = p_out[grp][d];
        h8tof8(XVout4[(size_t)s_out[grp][d] * U8 + lu], v);
        h8tof8(bout4[(size_t)l_out[grp][d] * U8 + lu], bb);
#pragma unroll
        for (int q = 0; q < 8; q++)
            acc[q] = fmaf(p, v[q] + bb[q], acc[q]);
    }
    int b = n / T_DIM, t = n % T_DIM;
    float sm = sent_mask[t * B_DIM + b];
#pragma unroll
    for (int q = 0; q < 8; q++)
        acc[q] = fmaxf(acc[q], 0.f) * sm;

    if (Y) {   // fp32 [t,b,u] membank output
        size_t base = ((size_t)t * B_DIM + b) * U4 + lu * 2;
        reinterpret_cast<float4*>(Y)[base] =
            make_float4(acc[0], acc[1], acc[2], acc[3]);
        reinterpret_cast<float4*>(Y)[base + 1] =
            make_float4(acc[4], acc[5], acc[6], acc[7]);
    }
    if (Yh) {  // fp16 node-major (next layer X)
        uint4 u;
        __half2 h;
        h = __floats2half2_rn(acc[0], acc[1]); u.x = *reinterpret_cast<uint32_t*>(&h);
        h = __floats2half2_rn(acc[2], acc[3]); u.y = *reinterpret_cast<uint32_t*>(&h);
        h = __floats2half2_rn(acc[4], acc[5]); u.z = *reinterpret_cast<uint32_t*>(&h);
        h = __floats2half2_rn(acc[6], acc[7]); u.w = *reinterpret_cast<uint32_t*>(&h);
        reinterpret_cast<uint4*>(Yh)[(size_t)n * U8 + lu] = u;
    }
}

// ---------------------------------------------------------------------------
// 4) enc[b] from membank layout
// ---------------------------------------------------------------------------
__global__ void enc_k(const float* __restrict__ MB,
                      const float* __restrict__ sent_mask,
                      float* __restrict__ enc)
{
    int b = blockIdx.x;
    int u = threadIdx.x;  // 0..63
    const float4* M4 = reinterpret_cast<const float4*>(MB);
    float4 s = make_float4(0.f, 0.f, 0.f, 0.f);
#pragma unroll 4
    for (int t = 0; t < T_DIM; t++) {
        float4 v = M4[((size_t)t * B_DIM + b) * U4 + u];
        s.x += v.x; s.y += v.y; s.z += v.z; s.w += v.w;
    }
    __shared__ float ms;
    if (u == 0) {
        float m = 0.f;
        for (int t = 0; t < T_DIM; t++) m += sent_mask[t * B_DIM + b];
        ms = m;
    }
    __syncthreads();
    float inv = 1.f / ms;
    s.x *= inv; s.y *= inv; s.z *= inv; s.w *= inv;
    reinterpret_cast<float4*>(enc)[b * U4 + u] = s;
}

// ---------------------------------------------------------------------------
// 5) h_all[k,b,w] = sum_u enc[b,u] * H[k,u,w]
// ---------------------------------------------------------------------------
__global__ void hall_k(const float* __restrict__ enc,
                       const float* __restrict__ H,
                       float* __restrict__ out)
{
    int k = blockIdx.y, b = blockIdx.x, w = threadIdx.x;
    __shared__ float es[U_DIM];
    es[w] = enc[b * U_DIM + w];
    __syncthreads();
    const float* Hk = H + (size_t)k * U_DIM * U_DIM;
    float acc = 0.f;
#pragma unroll 8
    for (int u = 0; u < U_DIM; u++)
        acc = fmaf(es[u], Hk[u * U_DIM + w], acc);
    out[((size_t)k * B_DIM + b) * U_DIM + w] = acc;
}

// ---------------------------------------------------------------------------
// Launch
// ---------------------------------------------------------------------------
extern "C" void kernel_launch(void* const* d_in, const int* in_sizes, int n_in,
                              void* d_out, int out_size)
{
    const int*   src       = (const int*)  d_in[0];
    const int*   arc_in    = (const int*)  d_in[1];
    const int*   arc_out   = (const int*)  d_in[2];
    const int*   lab_in    = (const int*)  d_in[3];
    const int*   lab_out   = (const int*)  d_in[4];
    const float* mask_in   = (const float*)d_in[5];
    const float* mask_out  = (const float*)d_in[6];
    const float* mask_loop = (const float*)d_in[7];
    const float* sent_mask = (const float*)d_in[8];
    const float* emb       = (const float*)d_in[9];
    const float* V_in      = (const float*)d_in[10];
    const float* b_in      = (const float*)d_in[11];
    const float* Vg_in     = (const float*)d_in[12];
    const float* bg_in     = (const float*)d_in[13];
    const float* V_out     = (const float*)d_in[14];
    const float* b_out     = (const float*)d_in[15];
    const float* Vg_out    = (const float*)d_in[16];
    const float* bg_out    = (const float*)d_in[17];
    const float* W_loop    = (const float*)d_in[18];
    const float* Wg_loop   = (const float*)d_in[19];
    const float* H         = (const float*)d_in[20];
    float* out = (float*)d_out;

    float *pgin, *pgout, *pgloop, *penc;
    __half *pXh, *pWh, *pbinh, *pbouth, *pXVin, *pXVout, *pXVloop;
    cudaGetSymbolAddress((void**)&pXh,     g_Xh);
    cudaGetSymbolAddress((void**)&pWh,     g_Wh);
    cudaGetSymbolAddress((void**)&pbinh,   g_binh);
    cudaGetSymbolAddress((void**)&pbouth,  g_bouth);
    cudaGetSymbolAddress((void**)&pXVin,   g_XVin);
    cudaGetSymbolAddress((void**)&pXVout,  g_XVout);
    cudaGetSymbolAddress((void**)&pXVloop, g_XVloop);
    cudaGetSymbolAddress((void**)&pgin,    g_gin);
    cudaGetSymbolAddress((void**)&pgout,   g_gout);
    cudaGetSymbolAddress((void**)&pgloop,  g_gloop);
    cudaGetSymbolAddress((void**)&penc,    g_enc);

    cudaFuncSetAttribute(gemm_gate_k,
                         cudaFuncAttributeMaxDynamicSharedMemorySize, SMEM_DYN);

    float* memOut = out + 4 * B_DIM * U_DIM;   // membank region of d_out

    cvtwT_k<<<dim3(8, 8, 6), dim3(32, 32)>>>(V_in, V_out, W_loop, pWh);
    cvtb_k<<<L_LAYERS * NL_LAB * U_DIM / 4 / 256, 256>>>(b_in, b_out,
                                                         pbinh, pbouth);
    embed_k<<<BT / 4, 256>>>(src, emb, pXh);

    for (int l = 0; l < L_LAYERS; l++) {
        const size_t gOff  = (size_t)l * U_DIM;
        const size_t bOff  = (size_t)l * NL_LAB * U_DIM;
        const size_t bgOff = (size_t)l * NL_LAB;
        const int last = (l == L_LAYERS - 1);

        gemm_gate_k<<<TOTAL_BLOCKS, GTHREADS, SMEM_DYN>>>(
            pXh, pWh + (size_t)l * 3 * WSZ,
            pXVin, pXVout, pXVloop,
            Vg_in + gOff, Vg_out + gOff, Wg_loop + gOff,
            pgin, pgout, pgloop);
        agg_k<<<BT / 8, 256>>>(pXVin, pXVout, pXVloop, pgin, pgout, pgloop,
                               arc_in, arc_out, lab_in, lab_out,
                               pbinh + bOff, bg_in + bgOff,
                               pbouth + bOff, bg_out + bgOff,
                               mask_in, mask_out, mask_loop, sent_mask,
                               last ? memOut : nullptr,
                               last ? nullptr : pXh);
    }

    enc_k<<<B_DIM, 64>>>(memOut, sent_mask, penc);
    hall_k<<<dim3(B_DIM, 4), U_DIM>>>(penc, H, out);
}